// round 14
// baseline (speedup 1.0000x reference)
#include <cuda_runtime.h>
#include <cuda_fp16.h>
#include <math.h>
#include <stdint.h>

// Problem constants
#define Bn  2
#define Sn  4096
#define En  512
#define Hn  8
#define Dn  64
#define E3  1536
#define Mrows (Bn * Sn)   // 8192

// Scratch (static device globals -- no allocation at runtime)
__device__ __half g_qkv[(size_t)Mrows * E3];        // [B*S,3E] fp16 (V unused)
__device__ __half g_vt [(size_t)Bn * Hn * Dn * Sn]; // V transposed [b][h][d][s]
__device__ __half g_att[(size_t)Mrows * En];        // attention out fp16
__device__ __half g_xh [(size_t)Mrows * En];        // x  fp16
__device__ __half g_w1h[(size_t)E3 * En];           // w1 fp16
__device__ __half g_w2h[(size_t)En * En];           // w2 fp16

// ===========================================================================
// Helpers
// ===========================================================================
__device__ __forceinline__ uint32_t smem_u32(const void* p) {
    uint32_t a;
    asm("{ .reg .u64 t; cvta.to.shared.u64 t, %1; cvt.u32.u64 %0, t; }"
        : "=r"(a) : "l"(p));
    return a;
}
__device__ __forceinline__ void cp16(uint32_t d, const void* s) {
    asm volatile("cp.async.cg.shared.global [%0], [%1], 16;"
                 :: "r"(d), "l"(s));
}
#define CP_COMMIT() asm volatile("cp.async.commit_group;" ::: "memory")
#define CP_WAIT0()  asm volatile("cp.async.wait_group 0;" ::: "memory")

__device__ __forceinline__ uint32_t h2u(__half2 h) {
    return *reinterpret_cast<uint32_t*>(&h);
}

// fp16 mma m16n8k16, fp32 accumulate
__device__ __forceinline__ void mma_f16(
    float& c0, float& c1, float& c2, float& c3,
    uint32_t a0, uint32_t a1, uint32_t a2, uint32_t a3,
    uint32_t b0, uint32_t b1)
{
    asm volatile(
        "mma.sync.aligned.m16n8k16.row.col.f32.f16.f16.f32 "
        "{%0,%1,%2,%3}, {%4,%5,%6,%7}, {%8,%9}, {%0,%1,%2,%3};"
        : "+f"(c0), "+f"(c1), "+f"(c2), "+f"(c3)
        : "r"(a0), "r"(a1), "r"(a2), "r"(a3), "r"(b0), "r"(b1));
}

// ldmatrix x4: four 8x8 b16 matrices
__device__ __forceinline__ void ldsm_x4(uint32_t& r0, uint32_t& r1,
                                        uint32_t& r2, uint32_t& r3,
                                        uint32_t addr)
{
    asm volatile("ldmatrix.sync.aligned.m8n8.x4.shared.b16 {%0,%1,%2,%3}, [%4];"
                 : "=r"(r0), "=r"(r1), "=r"(r2), "=r"(r3) : "r"(addr));
}

// ===========================================================================
// Convert x, w1, w2 to fp16 (8 floats per thread)
// ===========================================================================
#define NXf  (Mrows * En)          // 4194304
#define NW1f (E3 * En)             // 786432
#define NW2f (En * En)             // 262144

__global__ void __launch_bounds__(256)
cvt_h_kernel(const float* __restrict__ x, const float* __restrict__ w1,
             const float* __restrict__ w2)
{
    int i = blockIdx.x * 256 + threadIdx.x;
    int base = i * 8;
    const float* s;
    __half* d;
    if (base < NXf) {
        s = x + base;                 d = g_xh + base;
    } else if (base < NXf + NW1f) {
        s = w1 + (base - NXf);        d = g_w1h + (base - NXf);
    } else {
        s = w2 + (base - NXf - NW1f); d = g_w2h + (base - NXf - NW1f);
    }
    float4 v0 = *reinterpret_cast<const float4*>(s);
    float4 v1 = *reinterpret_cast<const float4*>(s + 4);
    uint4 o;
    o.x = h2u(__floats2half2_rn(v0.x, v0.y));
    o.y = h2u(__floats2half2_rn(v0.z, v0.w));
    o.z = h2u(__floats2half2_rn(v1.x, v1.y));
    o.w = h2u(__floats2half2_rn(v1.z, v1.w));
    *reinterpret_cast<uint4*>(d) = o;
}

// ===========================================================================
// fp16 GEMM, cp.async 2-stage, BK=64 halves, ldmatrix, m16n8k16.
// R14: CTA 64x128 (M x N), 256 threads / 8 warps (warp tile 32x32, wm 0..1,
// wn 0..3). acc = 32 regs/thread -> ~85 regs total -> >= 24 warps/SM
// (2x R12's 12). No fragment double-buffering (R13 regressed).
// C[M,N] = A[M,K] @ Bw[N,K]^T + bias[N].
// VT: qkv V-columns (nBase >= 1024) go TRANSPOSED (fp16) to g_vt.
// ===========================================================================
#define GPh 72   // smem pitch in halves (64 + 8); 144B rows -> conflict-free
#define GROWS 192                             // 64 A rows + 128 W rows
#define GSTAGE_B (GROWS * GPh * 2)            // 27648 B
#define GEMM_SMEM (2 * GSTAGE_B)              // 55296 B
#define TP 68    // transpose scratch pitch (floats, 64 rows + 4)

template<bool HALF_OUT, bool VT>
__device__ __forceinline__ void h16_gemm(
    const __half* __restrict__ A, const __half* __restrict__ Bw,
    const float* __restrict__ bias, void* __restrict__ Cv,
    int M, int N, int K)
{
    extern __shared__ float gsm[];
    const int tid  = threadIdx.x;
    const int lane = tid & 31;
    const int wid  = tid >> 5;         // 0..7
    const int wm   = wid >> 2;         // 0..1 (M halves of 64)
    const int wn   = wid & 3;          // 0..3 (N quarters of 128)
    const int lr   = lane >> 2;
    const int lc   = lane & 3;
    const int mBase = blockIdx.y * 64;
    const int nBase = blockIdx.x * 128;
    const uint32_t smb = smem_u32(gsm);

    float acc[2][4][4];
#pragma unroll
    for (int mt = 0; mt < 2; mt++)
#pragma unroll
        for (int nt = 0; nt < 4; nt++)
#pragma unroll
            for (int i = 0; i < 4; i++) acc[mt][nt][i] = 0.0f;

    const __half* Abase = A  + (size_t)mBase * K;
    const __half* Wbase = Bw + (size_t)nBase * K;

    // ldmatrix per-lane offsets (bytes within a stage)
    const int lrow16 = lane & 15;
    const int kgrpA  = (lane >> 4) * 8;                       // halves
    const int rowB2  = (lane & 7) + ((lane >> 4) & 1) * 8;
    const int kofB8  = ((lane >> 3) & 1) * 8;                 // halves
    uint32_t offA[2], offB[2];
#pragma unroll
    for (int mt = 0; mt < 2; mt++)
        offA[mt] = (uint32_t)(((wm * 32 + mt * 16 + lrow16) * GPh + kgrpA) * 2);
#pragma unroll
    for (int p = 0; p < 2; p++)
        offB[p] = (uint32_t)((64 * GPh + (wn * 32 + p * 16 + rowB2) * GPh + kofB8) * 2);

    const int nIter = K >> 6;
    // Loader: 6 cp16 per thread per stage (192 rows x 64 halves, 256 thr)
    auto issue = [&](int it, int s) {
        if (it < nIter) {
            uint32_t sb = smb + (uint32_t)s * GSTAGE_B;
            int kt = it << 6;
#pragma unroll
            for (int i = 0; i < 6; i++) {
                int f   = tid + i * 256;       // 0..1535
                int row = f >> 3;              // 0..191
                int c8  = (f & 7) << 3;        // 0..56 halves
                const __half* src = (row < 64)
                    ? (Abase + (size_t)row * K + kt + c8)
                    : (Wbase + (size_t)(row - 64) * K + kt + c8);
                cp16(sb + (uint32_t)(row * GPh + c8) * 2u, src);
            }
        }
        CP_COMMIT();
    };
    issue(0, 0);

    for (int it = 0; it < nIter; it++) {
        CP_WAIT0();
        __syncthreads();
        issue(it + 1, (it + 1) & 1);

        const uint32_t stb = smb + (uint32_t)(it & 1) * GSTAGE_B;
#pragma unroll
        for (int k16 = 0; k16 < 4; k16++) {
            const uint32_t kb = (uint32_t)(k16 * 32);   // 16 halves = 32 B
            uint32_t af[2][4], bf[4][2];
#pragma unroll
            for (int mt = 0; mt < 2; mt++)
                ldsm_x4(af[mt][0], af[mt][1], af[mt][2], af[mt][3],
                        stb + offA[mt] + kb);
#pragma unroll
            for (int p = 0; p < 2; p++)
                ldsm_x4(bf[2 * p][0], bf[2 * p][1],
                        bf[2 * p + 1][0], bf[2 * p + 1][1],
                        stb + offB[p] + kb);
#pragma unroll
            for (int mt = 0; mt < 2; mt++)
#pragma unroll
                for (int nt = 0; nt < 4; nt++)
                    mma_f16(acc[mt][nt][0], acc[mt][nt][1],
                            acc[mt][nt][2], acc[mt][nt][3],
                            af[mt][0], af[mt][1], af[mt][2], af[mt][3],
                            bf[nt][0], bf[nt][1]);
        }
    }

    if (VT && nBase >= 2 * En) {
        // ---- V tile (64 x 128): bias, transpose via smem, write g_vt ----
        CP_WAIT0();
        __syncthreads();
        float* T = gsm;                    // [128 cols][TP rows(64+4)]
#pragma unroll
        for (int mt = 0; mt < 2; mt++) {
            const int r0 = wm * 32 + mt * 16 + lr;
#pragma unroll
            for (int nt = 0; nt < 4; nt++) {
                const int c = wn * 32 + nt * 8 + 2 * lc;
                const float bx = bias[nBase + c];
                const float by = bias[nBase + c + 1];
                T[c * TP + r0]           = acc[mt][nt][0] + bx;
                T[(c + 1) * TP + r0]     = acc[mt][nt][1] + by;
                T[c * TP + r0 + 8]       = acc[mt][nt][2] + bx;
                T[(c + 1) * TP + r0 + 8] = acc[mt][nt][3] + by;
            }
        }
        __syncthreads();
        const int bb = mBase >> 12;
        const int s0 = mBase & (Sn - 1);
#pragma unroll
        for (int i = 0; i < 4; i++) {
            int f  = tid + i * 256;        // 0..1023
            int c  = f >> 3;               // 0..127 local col (h,d)
            int r8 = (f & 7) << 3;         // 0..56 local row (seq)
            int col = nBase - 2 * En + c;
            int h = col >> 6, d = col & 63;
            const float* tp = T + c * TP + r8;
            uint4 o;
            o.x = h2u(__floats2half2_rn(tp[0], tp[1]));
            o.y = h2u(__floats2half2_rn(tp[2], tp[3]));
            o.z = h2u(__floats2half2_rn(tp[4], tp[5]));
            o.w = h2u(__floats2half2_rn(tp[6], tp[7]));
            *reinterpret_cast<uint4*>(
                g_vt + (((size_t)bb * Hn + h) * Dn + d) * Sn + s0 + r8) = o;
        }
        return;
    }

    // ---- normal epilogue ----
#pragma unroll
    for (int mt = 0; mt < 2; mt++) {
        const int row0 = mBase + wm * 32 + mt * 16 + lr;
#pragma unroll
        for (int nt = 0; nt < 4; nt++) {
            const int col = nBase + wn * 32 + nt * 8 + 2 * lc;
            const float bx = bias[col];
            const float by = bias[col + 1];
            float v0 = acc[mt][nt][0] + bx, v1 = acc[mt][nt][1] + by;
            float v2 = acc[mt][nt][2] + bx, v3 = acc[mt][nt][3] + by;
            if (HALF_OUT) {
                __half* C = (__half*)Cv;
                *reinterpret_cast<uint32_t*>(C + (size_t)row0 * N + col) =
                    h2u(__floats2half2_rn(v0, v1));
                *reinterpret_cast<uint32_t*>(C + (size_t)(row0 + 8) * N + col) =
                    h2u(__floats2half2_rn(v2, v3));
            } else {
                float* C = (float*)Cv;
                *reinterpret_cast<float2*>(C + (size_t)row0 * N + col) =
                    make_float2(v0, v1);
                *reinterpret_cast<float2*>(C + (size_t)(row0 + 8) * N + col) =
                    make_float2(v2, v3);
            }
        }
    }
}

__global__ void __launch_bounds__(256, 3)
gemm_qkv_kernel(const float* __restrict__ b1)
{
    h16_gemm<true, true>(g_xh, g_w1h, b1, g_qkv, Mrows, E3, En);
}

__global__ void __launch_bounds__(256, 3)
gemm_out_kernel(const float* __restrict__ b2, float* __restrict__ out)
{
    h16_gemm<false, false>(g_att, g_w2h, b2, out, Mrows, En, En);
}

// ===========================================================================
// FlashAttention-2, Gaussian-bias windowed, fp16 m16n8k16 HMMA.
// P's fp16 A-fragment layout == pairs of S C-fragments -> zero shuffles.
// Window W = 11 t^2 + 64 (dropped mass < 4e-10).
// Grid (Sn/64, Hn, Bn), 128 threads, 4 CTAs/SM.  (unchanged from R11)
// ===========================================================================
#define BR   64
#define BC   64
#define KVPh 72                         // smem pitch (halves)
#define NKB  (Sn / BC)
#define ATTN_THREADS 128
#define KV_TILE_B (BC * KVPh * 2)       // 9216 B per operand tile
#define ATTN_SMEM (2 * 2 * KV_TILE_B)   // 36864 B

__global__ void __launch_bounds__(ATTN_THREADS, 4)
attn_fa2_kernel(const float* __restrict__ t)
{
    extern __shared__ float sm[];
    const uint32_t smb = smem_u32(sm);

    const int tid  = threadIdx.x;
    const int lane = tid & 31;
    const int wid  = tid >> 5;             // 0..3
    const int qt = blockIdx.x, h = blockIdx.y, b = blockIdx.z;
    const int q0 = qt * BR;
    const int qw = q0 + wid * 16;

    const int lr = lane >> 2;
    const int lc = lane & 3;

    const float tt = t[h];
    const float sig = tt * tt;
    const float ninv = -1.0f / (2.0f * sig * sig);

    const float Wf = fminf(11.0f * sig + 64.0f, (float)Sn);
    const int   W  = (int)Wf;
    const int kb_lo = max(0, (q0 - W) >> 6);
    const int kb_hi = min(NKB - 1, (q0 + BR - 1 + W) >> 6);

    const __half* srcVbase = g_vt + ((size_t)b * Hn + h) * Dn * Sn;
    auto issue_kv = [&](int k0, int buf) {
        const __half* srcK = g_qkv + En + (size_t)(b * Sn + k0) * E3 + h * Dn;
        const __half* srcV = srcVbase + k0;
        uint32_t sb = smb + (uint32_t)buf * (2u * KV_TILE_B);
#pragma unroll
        for (int i = 0; i < 8; i++) {
            int f   = i * ATTN_THREADS + tid;   // 0..1023
            int sel = f >> 9;
            int idx = f & 511;
            int row = idx >> 3;                 // 0..63
            int c8  = (idx & 7) << 3;           // 0..56 halves
            const __half* src = sel ? (srcV + (size_t)row * Sn + c8)
                                    : (srcK + (size_t)row * E3 + c8);
            uint32_t dst = sb + (uint32_t)((sel * BC + row) * KVPh + c8) * 2u;
            cp16(dst, src);
        }
    };

    const int rowB2 = (lane & 7) + ((lane >> 4) & 1) * 8;
    const int kofB8 = ((lane >> 3) & 1) * 8;
    uint32_t offK[4], offV[4];
#pragma unroll
    for (int p = 0; p < 4; p++) {
        offK[p] = (uint32_t)(((p * 16 + rowB2) * KVPh + kofB8) * 2);
        offV[p] = offK[p] + (uint32_t)KV_TILE_B;
    }

    uint32_t qa[4][4];
    {
        const __half2 s125 = __float2half2_rn(0.125f);
        const __half* qp  = g_qkv + (size_t)(b * Sn + qw + lr) * E3 + h * Dn;
        const __half* qp8 = qp + 8 * E3;
#pragma unroll
        for (int kt = 0; kt < 4; kt++) {
            int k0h = kt * 16 + 2 * lc;
            qa[kt][0] = h2u(__hmul2(*(const __half2*)(qp  + k0h),     s125));
            qa[kt][1] = h2u(__hmul2(*(const __half2*)(qp8 + k0h),     s125));
            qa[kt][2] = h2u(__hmul2(*(const __half2*)(qp  + k0h + 8), s125));
            qa[kt][3] = h2u(__hmul2(*(const __half2*)(qp8 + k0h + 8), s125));
        }
    }

    float o[8][4];
#pragma unroll
    for (int nt = 0; nt < 8; nt++)
#pragma unroll
        for (int i = 0; i < 4; i++) o[nt][i] = 0.0f;
    float m0 = -INFINITY, m1 = -INFINITY;
    float l0 = 0.0f, l1 = 0.0f;

    issue_kv(kb_lo * BC, 0);
    CP_COMMIT();

    const int colb = 2 * lc;

    int cur = 0;
    for (int kb = kb_lo; kb <= kb_hi; kb++) {
        const int k0 = kb * BC;

        CP_WAIT0();
        __syncthreads();
        if (kb + 1 <= kb_hi) issue_kv(k0 + BC, cur ^ 1);
        CP_COMMIT();

        const uint32_t Kb = smb + (uint32_t)cur * (2u * KV_TILE_B);

        // ---- S = Q @ K^T ----
        float sc[8][4];
#pragma unroll
        for (int nt = 0; nt < 8; nt++)
#pragma unroll
            for (int i = 0; i < 4; i++) sc[nt][i] = 0.0f;

#pragma unroll
        for (int kt = 0; kt < 4; kt++) {
            uint32_t kf[8][2];
#pragma unroll
            for (int p = 0; p < 4; p++)
                ldsm_x4(kf[2 * p][0], kf[2 * p][1],
                        kf[2 * p + 1][0], kf[2 * p + 1][1],
                        Kb + offK[p] + (uint32_t)(kt * 32));
#pragma unroll
            for (int nt = 0; nt < 8; nt++)
                mma_f16(sc[nt][0], sc[nt][1], sc[nt][2], sc[nt][3],
                        qa[kt][0], qa[kt][1], qa[kt][2], qa[kt][3],
                        kf[nt][0], kf[nt][1]);
        }

        // ---- Gaussian bias + online softmax ----
        const float d0f = (float)(qw + lr - k0);
        const float d1f = d0f + 8.0f;
        float rmax0 = -INFINITY, rmax1 = -INFINITY;
#pragma unroll
        for (int nt = 0; nt < 8; nt++) {
#pragma unroll
            for (int e = 0; e < 2; e++) {
                float cj = (float)(nt * 8 + colb + e);
                float fd0 = d0f - cj;
                float fd1 = d1f - cj;
                sc[nt][e]     = fmaf(fd0 * fd0, ninv, sc[nt][e]);
                sc[nt][e + 2] = fmaf(fd1 * fd1, ninv, sc[nt][e + 2]);
                rmax0 = fmaxf(rmax0, sc[nt][e]);
                rmax1 = fmaxf(rmax1, sc[nt][e + 2]);
            }
        }
        rmax0 = fmaxf(rmax0, __shfl_xor_sync(0xffffffffu, rmax0, 1));
        rmax0 = fmaxf(rmax0, __shfl_xor_sync(0xffffffffu, rmax0, 2));
        rmax1 = fmaxf(rmax1, __shfl_xor_sync(0xffffffffu, rmax1, 1));
        rmax1 = fmaxf(rmax1, __shfl_xor_sync(0xffffffffu, rmax1, 2));

        const float mn0 = fmaxf(m0, rmax0);
        const float mn1 = fmaxf(m1, rmax1);
        const float corr0 = __expf(m0 - mn0);
        const float corr1 = __expf(m1 - mn1);
        m0 = mn0; m1 = mn1;

        uint32_t plo[8], phi[8];
        float ls0 = 0.0f, ls1 = 0.0f;
#pragma unroll
        for (int nt = 0; nt < 8; nt++) {
            float p0 = __expf(sc[nt][0] - mn0);
            float p1 = __expf(sc[nt][1] - mn0);
            float p2 = __expf(sc[nt][2] - mn1);
            float p3 = __expf(sc[nt][3] - mn1);
            __half2 hl = __floats2half2_rn(p0, p1);
            __half2 hh = __floats2half2_rn(p2, p3);
            float2 fl = __half22float2(hl);
            float2 fh = __half22float2(hh);
            ls0 += fl.x + fl.y;
            ls1 += fh.x + fh.y;
            plo[nt] = h2u(hl);
            phi[nt] = h2u(hh);
        }
        l0 = l0 * corr0 + ls0;
        l1 = l1 * corr1 + ls1;

        if (__ballot_sync(0xffffffffu, (corr0 != 1.0f) | (corr1 != 1.0f))) {
#pragma unroll
            for (int nt = 0; nt < 8; nt++) {
                o[nt][0] *= corr0; o[nt][1] *= corr0;
                o[nt][2] *= corr1; o[nt][3] *= corr1;
            }
        }

        // ---- O += P @ V ----
#pragma unroll
        for (int kt2 = 0; kt2 < 4; kt2++) {
            uint32_t a0 = plo[2 * kt2];
            uint32_t a1 = phi[2 * kt2];
            uint32_t a2 = plo[2 * kt2 + 1];
            uint32_t a3 = phi[2 * kt2 + 1];

            uint32_t vf[8][2];
#pragma unroll
            for (int p = 0; p < 4; p++)
                ldsm_x4(vf[2 * p][0], vf[2 * p][1],
                        vf[2 * p + 1][0], vf[2 * p + 1][1],
                        Kb + offV[p] + (uint32_t)(kt2 * 32));
#pragma unroll
            for (int nt = 0; nt < 8; nt++)
                mma_f16(o[nt][0], o[nt][1], o[nt][2], o[nt][3],
                        a0, a1, a2, a3, vf[nt][0], vf[nt][1]);
        }

        cur ^= 1;
    }

    l0 += __shfl_xor_sync(0xffffffffu, l0, 1);
    l0 += __shfl_xor_sync(0xffffffffu, l0, 2);
    l1 += __shfl_xor_sync(0xffffffffu, l1, 1);
    l1 += __shfl_xor_sync(0xffffffffu, l1, 2);
    const float il0 = 1.0f / l0;
    const float il1 = 1.0f / l1;

    __half* op0 = g_att + (size_t)(b * Sn + qw + lr) * En + h * Dn + colb;
    __half* op1 = op0 + 8 * En;
#pragma unroll
    for (int nt = 0; nt < 8; nt++) {
        *reinterpret_cast<uint32_t*>(op0 + nt * 8) =
            h2u(__floats2half2_rn(o[nt][0] * il0, o[nt][1] * il0));
        *reinterpret_cast<uint32_t*>(op1 + nt * 8) =
            h2u(__floats2half2_rn(o[nt][2] * il1, o[nt][3] * il1));
    }
}

// ===========================================================================
// Launch
// ===========================================================================
extern "C" void kernel_launch(void* const* d_in, const int* in_sizes, int n_in,
                              void* d_out, int out_size)
{
    const float* x  = (const float*)d_in[0];
    const float* w1 = (const float*)d_in[1];
    const float* b1 = (const float*)d_in[2];
    const float* w2 = (const float*)d_in[3];
    const float* b2 = (const float*)d_in[4];
    const float* t  = (const float*)d_in[5];
    float* out = (float*)d_out;
    (void)in_sizes; (void)n_in; (void)out_size;

    cvt_h_kernel<<<(NXf + NW1f + NW2f) / (256 * 8), 256>>>(x, w1, w2);

    cudaFuncSetAttribute(gemm_qkv_kernel,
                         cudaFuncAttributeMaxDynamicSharedMemorySize, GEMM_SMEM);
    cudaFuncSetAttribute(gemm_out_kernel,
                         cudaFuncAttributeMaxDynamicSharedMemorySize, GEMM_SMEM);
    cudaFuncSetAttribute(attn_fa2_kernel,
                         cudaFuncAttributeMaxDynamicSharedMemorySize, ATTN_SMEM);

    gemm_qkv_kernel<<<dim3(E3 / 128, Mrows / 64), 256, GEMM_SMEM>>>(b1);

    attn_fa2_kernel<<<dim3(Sn / BR, Hn, Bn), ATTN_THREADS, ATTN_SMEM>>>(t);

    gemm_out_kernel<<<dim3(En / 128, Mrows / 64), 256, GEMM_SMEM>>>(b2, out);
}

// round 15
// speedup vs baseline: 1.1151x; 1.1151x over previous
#include <cuda_runtime.h>
#include <cuda_fp16.h>
#include <math.h>
#include <stdint.h>

// Problem constants
#define Bn  2
#define Sn  4096
#define En  512
#define Hn  8
#define Dn  64
#define E3  1536
#define Mrows (Bn * Sn)   // 8192

// Scratch (static device globals -- no allocation at runtime)
__device__ __half g_qkv[(size_t)Mrows * E3];        // [B*S,3E] fp16 (V unused)
__device__ __half g_vt [(size_t)Bn * Hn * Dn * Sn]; // V transposed [b][h][d][s]
__device__ __half g_att[(size_t)Mrows * En];        // attention out fp16
__device__ __half g_xh [(size_t)Mrows * En];        // x  fp16
__device__ __half g_w1h[(size_t)E3 * En];           // w1 fp16
__device__ __half g_w2h[(size_t)En * En];           // w2 fp16

// ===========================================================================
// Helpers
// ===========================================================================
__device__ __forceinline__ uint32_t smem_u32(const void* p) {
    uint32_t a;
    asm("{ .reg .u64 t; cvta.to.shared.u64 t, %1; cvt.u32.u64 %0, t; }"
        : "=r"(a) : "l"(p));
    return a;
}
__device__ __forceinline__ void cp16(uint32_t d, const void* s) {
    asm volatile("cp.async.cg.shared.global [%0], [%1], 16;"
                 :: "r"(d), "l"(s));
}
#define CP_COMMIT() asm volatile("cp.async.commit_group;" ::: "memory")
#define CP_WAIT0()  asm volatile("cp.async.wait_group 0;" ::: "memory")

__device__ __forceinline__ uint32_t h2u(__half2 h) {
    return *reinterpret_cast<uint32_t*>(&h);
}

// fp16 mma m16n8k16, fp32 accumulate
__device__ __forceinline__ void mma_f16(
    float& c0, float& c1, float& c2, float& c3,
    uint32_t a0, uint32_t a1, uint32_t a2, uint32_t a3,
    uint32_t b0, uint32_t b1)
{
    asm volatile(
        "mma.sync.aligned.m16n8k16.row.col.f32.f16.f16.f32 "
        "{%0,%1,%2,%3}, {%4,%5,%6,%7}, {%8,%9}, {%0,%1,%2,%3};"
        : "+f"(c0), "+f"(c1), "+f"(c2), "+f"(c3)
        : "r"(a0), "r"(a1), "r"(a2), "r"(a3), "r"(b0), "r"(b1));
}

// ldmatrix x4: four 8x8 b16 matrices
__device__ __forceinline__ void ldsm_x4(uint32_t& r0, uint32_t& r1,
                                        uint32_t& r2, uint32_t& r3,
                                        uint32_t addr)
{
    asm volatile("ldmatrix.sync.aligned.m8n8.x4.shared.b16 {%0,%1,%2,%3}, [%4];"
                 : "=r"(r0), "=r"(r1), "=r"(r2), "=r"(r3) : "r"(addr));
}

// ===========================================================================
// Convert x, w1, w2 to fp16 (8 floats per thread)
// ===========================================================================
#define NXf  (Mrows * En)          // 4194304
#define NW1f (E3 * En)             // 786432
#define NW2f (En * En)             // 262144

__global__ void __launch_bounds__(256)
cvt_h_kernel(const float* __restrict__ x, const float* __restrict__ w1,
             const float* __restrict__ w2)
{
    int i = blockIdx.x * 256 + threadIdx.x;
    int base = i * 8;
    const float* s;
    __half* d;
    if (base < NXf) {
        s = x + base;                 d = g_xh + base;
    } else if (base < NXf + NW1f) {
        s = w1 + (base - NXf);        d = g_w1h + (base - NXf);
    } else {
        s = w2 + (base - NXf - NW1f); d = g_w2h + (base - NXf - NW1f);
    }
    float4 v0 = *reinterpret_cast<const float4*>(s);
    float4 v1 = *reinterpret_cast<const float4*>(s + 4);
    uint4 o;
    o.x = h2u(__floats2half2_rn(v0.x, v0.y));
    o.y = h2u(__floats2half2_rn(v0.z, v0.w));
    o.z = h2u(__floats2half2_rn(v1.x, v1.y));
    o.w = h2u(__floats2half2_rn(v1.z, v1.w));
    *reinterpret_cast<uint4*>(d) = o;
}

// ===========================================================================
// fp16 GEMM, cp.async 2-stage, BK=64 halves, ldmatrix, m16n8k16.
// R12-exact config (best measured): CTA 64x128, 128 threads / 4 warps
// (warp tile 64x32, wm=0). mOff selects the batch half (stream split).
// C[M,N] = A[M,K] @ Bw[N,K]^T + bias[N].
// VT: qkv V-columns (nBase >= 1024) go TRANSPOSED (fp16) to g_vt.
// ===========================================================================
#define GPh 72   // smem pitch in halves (64 + 8); 144B rows -> conflict-free
#define GROWS 192                             // 64 A rows + 128 W rows
#define GSTAGE_B (GROWS * GPh * 2)            // 27648 B
#define GEMM_SMEM (2 * GSTAGE_B)              // 55296 B
#define TP 68    // transpose scratch pitch (floats, 64 rows + 4)

template<bool HALF_OUT, bool VT>
__device__ __forceinline__ void h16_gemm(
    const __half* __restrict__ A, const __half* __restrict__ Bw,
    const float* __restrict__ bias, void* __restrict__ Cv,
    int M, int N, int K, int mOff)
{
    extern __shared__ float gsm[];
    const int tid  = threadIdx.x;
    const int lane = tid & 31;
    const int wid  = tid >> 5;         // 0..3
    const int wn   = wid;              // all warps tile N; wm = 0
    const int lr   = lane >> 2;
    const int lc   = lane & 3;
    const int mBase = blockIdx.y * 64 + mOff;
    const int nBase = blockIdx.x * 128;
    const uint32_t smb = smem_u32(gsm);

    float acc[4][4][4];
#pragma unroll
    for (int mt = 0; mt < 4; mt++)
#pragma unroll
        for (int nt = 0; nt < 4; nt++)
#pragma unroll
            for (int i = 0; i < 4; i++) acc[mt][nt][i] = 0.0f;

    const __half* Abase = A  + (size_t)mBase * K;
    const __half* Wbase = Bw + (size_t)nBase * K;

    // ldmatrix per-lane offsets (bytes within a stage)
    const int lrow16 = lane & 15;
    const int kgrpA  = (lane >> 4) * 8;                       // halves
    const int rowB2  = (lane & 7) + ((lane >> 4) & 1) * 8;
    const int kofB8  = ((lane >> 3) & 1) * 8;                 // halves
    uint32_t offA[4], offB[2];
#pragma unroll
    for (int mt = 0; mt < 4; mt++)
        offA[mt] = (uint32_t)(((mt * 16 + lrow16) * GPh + kgrpA) * 2);
#pragma unroll
    for (int p = 0; p < 2; p++)
        offB[p] = (uint32_t)((64 * GPh + (wn * 32 + p * 16 + rowB2) * GPh + kofB8) * 2);

    const int nIter = K >> 6;
    // Loader: 12 cp16 per thread per stage (192 rows x 64 halves)
    auto issue = [&](int it, int s) {
        if (it < nIter) {
            uint32_t sb = smb + (uint32_t)s * GSTAGE_B;
            int kt = it << 6;
#pragma unroll
            for (int i = 0; i < 12; i++) {
                int f   = tid + i * 128;       // 0..1535
                int row = f >> 3;              // 0..191
                int c8  = (f & 7) << 3;        // 0..56 halves
                const __half* src = (row < 64)
                    ? (Abase + (size_t)row * K + kt + c8)
                    : (Wbase + (size_t)(row - 64) * K + kt + c8);
                cp16(sb + (uint32_t)(row * GPh + c8) * 2u, src);
            }
        }
        CP_COMMIT();
    };
    issue(0, 0);

    for (int it = 0; it < nIter; it++) {
        CP_WAIT0();
        __syncthreads();
        issue(it + 1, (it + 1) & 1);

        const uint32_t stb = smb + (uint32_t)(it & 1) * GSTAGE_B;
#pragma unroll
        for (int k16 = 0; k16 < 4; k16++) {
            const uint32_t kb = (uint32_t)(k16 * 32);   // 16 halves = 32 B
            uint32_t af[4][4], bf[4][2];
#pragma unroll
            for (int mt = 0; mt < 4; mt++)
                ldsm_x4(af[mt][0], af[mt][1], af[mt][2], af[mt][3],
                        stb + offA[mt] + kb);
#pragma unroll
            for (int p = 0; p < 2; p++)
                ldsm_x4(bf[2 * p][0], bf[2 * p][1],
                        bf[2 * p + 1][0], bf[2 * p + 1][1],
                        stb + offB[p] + kb);
#pragma unroll
            for (int mt = 0; mt < 4; mt++)
#pragma unroll
                for (int nt = 0; nt < 4; nt++)
                    mma_f16(acc[mt][nt][0], acc[mt][nt][1],
                            acc[mt][nt][2], acc[mt][nt][3],
                            af[mt][0], af[mt][1], af[mt][2], af[mt][3],
                            bf[nt][0], bf[nt][1]);
        }
    }

    if (VT && nBase >= 2 * En) {
        // ---- V tile (64 x 128): bias, transpose via smem, write g_vt ----
        CP_WAIT0();
        __syncthreads();
        float* T = gsm;                    // [128 cols][TP rows(64+4)]
#pragma unroll
        for (int mt = 0; mt < 4; mt++) {
            const int r0 = mt * 16 + lr;
#pragma unroll
            for (int nt = 0; nt < 4; nt++) {
                const int c = wn * 32 + nt * 8 + 2 * lc;
                const float bx = bias[nBase + c];
                const float by = bias[nBase + c + 1];
                T[c * TP + r0]           = acc[mt][nt][0] + bx;
                T[(c + 1) * TP + r0]     = acc[mt][nt][1] + by;
                T[c * TP + r0 + 8]       = acc[mt][nt][2] + bx;
                T[(c + 1) * TP + r0 + 8] = acc[mt][nt][3] + by;
            }
        }
        __syncthreads();
        const int bb = mBase >> 12;
        const int s0 = mBase & (Sn - 1);
#pragma unroll
        for (int i = 0; i < 8; i++) {
            int f  = tid + i * 128;        // 0..1023
            int c  = f >> 3;               // 0..127 local col (h,d)
            int r8 = (f & 7) << 3;         // 0..56 local row (seq)
            int col = nBase - 2 * En + c;
            int h = col >> 6, d = col & 63;
            const float* tp = T + c * TP + r8;
            uint4 o;
            o.x = h2u(__floats2half2_rn(tp[0], tp[1]));
            o.y = h2u(__floats2half2_rn(tp[2], tp[3]));
            o.z = h2u(__floats2half2_rn(tp[4], tp[5]));
            o.w = h2u(__floats2half2_rn(tp[6], tp[7]));
            *reinterpret_cast<uint4*>(
                g_vt + (((size_t)bb * Hn + h) * Dn + d) * Sn + s0 + r8) = o;
        }
        return;
    }

    // ---- normal epilogue ----
#pragma unroll
    for (int mt = 0; mt < 4; mt++) {
        const int row0 = mBase + mt * 16 + lr;
#pragma unroll
        for (int nt = 0; nt < 4; nt++) {
            const int col = nBase + wn * 32 + nt * 8 + 2 * lc;
            const float bx = bias[col];
            const float by = bias[col + 1];
            float v0 = acc[mt][nt][0] + bx, v1 = acc[mt][nt][1] + by;
            float v2 = acc[mt][nt][2] + bx, v3 = acc[mt][nt][3] + by;
            if (HALF_OUT) {
                __half* C = (__half*)Cv;
                *reinterpret_cast<uint32_t*>(C + (size_t)row0 * N + col) =
                    h2u(__floats2half2_rn(v0, v1));
                *reinterpret_cast<uint32_t*>(C + (size_t)(row0 + 8) * N + col) =
                    h2u(__floats2half2_rn(v2, v3));
            } else {
                float* C = (float*)Cv;
                *reinterpret_cast<float2*>(C + (size_t)row0 * N + col) =
                    make_float2(v0, v1);
                *reinterpret_cast<float2*>(C + (size_t)(row0 + 8) * N + col) =
                    make_float2(v2, v3);
            }
        }
    }
}

__global__ void __launch_bounds__(128, 4)
gemm_qkv_kernel(const float* __restrict__ b1, int mOff)
{
    h16_gemm<true, true>(g_xh, g_w1h, b1, g_qkv, Mrows, E3, En, mOff);
}

__global__ void __launch_bounds__(128, 4)
gemm_out_kernel(const float* __restrict__ b2, float* __restrict__ out, int mOff)
{
    h16_gemm<false, false>(g_att, g_w2h, b2, out, Mrows, En, En, mOff);
}

// ===========================================================================
// FlashAttention-2, Gaussian-bias windowed, fp16 m16n8k16 HMMA.
// P's fp16 A-fragment layout == pairs of S C-fragments -> zero shuffles.
// Window W = 11 t^2 + 64 (dropped mass < 4e-10).
// Grid (Sn/64, Hn, 1) per batch (batch passed as param for stream split),
// 128 threads, 4 CTAs/SM.
// ===========================================================================
#define BR   64
#define BC   64
#define KVPh 72                         // smem pitch (halves)
#define NKB  (Sn / BC)
#define ATTN_THREADS 128
#define KV_TILE_B (BC * KVPh * 2)       // 9216 B per operand tile
#define ATTN_SMEM (2 * 2 * KV_TILE_B)   // 36864 B

__global__ void __launch_bounds__(ATTN_THREADS, 4)
attn_fa2_kernel(const float* __restrict__ t, int b)
{
    extern __shared__ float sm[];
    const uint32_t smb = smem_u32(sm);

    const int tid  = threadIdx.x;
    const int lane = tid & 31;
    const int wid  = tid >> 5;             // 0..3
    const int qt = blockIdx.x, h = blockIdx.y;
    const int q0 = qt * BR;
    const int qw = q0 + wid * 16;

    const int lr = lane >> 2;
    const int lc = lane & 3;

    const float tt = t[h];
    const float sig = tt * tt;
    const float ninv = -1.0f / (2.0f * sig * sig);

    const float Wf = fminf(11.0f * sig + 64.0f, (float)Sn);
    const int   W  = (int)Wf;
    const int kb_lo = max(0, (q0 - W) >> 6);
    const int kb_hi = min(NKB - 1, (q0 + BR - 1 + W) >> 6);

    const __half* srcVbase = g_vt + ((size_t)b * Hn + h) * Dn * Sn;
    auto issue_kv = [&](int k0, int buf) {
        const __half* srcK = g_qkv + En + (size_t)(b * Sn + k0) * E3 + h * Dn;
        const __half* srcV = srcVbase + k0;
        uint32_t sb = smb + (uint32_t)buf * (2u * KV_TILE_B);
#pragma unroll
        for (int i = 0; i < 8; i++) {
            int f   = i * ATTN_THREADS + tid;   // 0..1023
            int sel = f >> 9;
            int idx = f & 511;
            int row = idx >> 3;                 // 0..63
            int c8  = (idx & 7) << 3;           // 0..56 halves
            const __half* src = sel ? (srcV + (size_t)row * Sn + c8)
                                    : (srcK + (size_t)row * E3 + c8);
            uint32_t dst = sb + (uint32_t)((sel * BC + row) * KVPh + c8) * 2u;
            cp16(dst, src);
        }
    };

    const int rowB2 = (lane & 7) + ((lane >> 4) & 1) * 8;
    const int kofB8 = ((lane >> 3) & 1) * 8;
    uint32_t offK[4], offV[4];
#pragma unroll
    for (int p = 0; p < 4; p++) {
        offK[p] = (uint32_t)(((p * 16 + rowB2) * KVPh + kofB8) * 2);
        offV[p] = offK[p] + (uint32_t)KV_TILE_B;
    }

    uint32_t qa[4][4];
    {
        const __half2 s125 = __float2half2_rn(0.125f);
        const __half* qp  = g_qkv + (size_t)(b * Sn + qw + lr) * E3 + h * Dn;
        const __half* qp8 = qp + 8 * E3;
#pragma unroll
        for (int kt = 0; kt < 4; kt++) {
            int k0h = kt * 16 + 2 * lc;
            qa[kt][0] = h2u(__hmul2(*(const __half2*)(qp  + k0h),     s125));
            qa[kt][1] = h2u(__hmul2(*(const __half2*)(qp8 + k0h),     s125));
            qa[kt][2] = h2u(__hmul2(*(const __half2*)(qp  + k0h + 8), s125));
            qa[kt][3] = h2u(__hmul2(*(const __half2*)(qp8 + k0h + 8), s125));
        }
    }

    float o[8][4];
#pragma unroll
    for (int nt = 0; nt < 8; nt++)
#pragma unroll
        for (int i = 0; i < 4; i++) o[nt][i] = 0.0f;
    float m0 = -INFINITY, m1 = -INFINITY;
    float l0 = 0.0f, l1 = 0.0f;

    issue_kv(kb_lo * BC, 0);
    CP_COMMIT();

    const int colb = 2 * lc;

    int cur = 0;
    for (int kb = kb_lo; kb <= kb_hi; kb++) {
        const int k0 = kb * BC;

        CP_WAIT0();
        __syncthreads();
        if (kb + 1 <= kb_hi) issue_kv(k0 + BC, cur ^ 1);
        CP_COMMIT();

        const uint32_t Kb = smb + (uint32_t)cur * (2u * KV_TILE_B);

        // ---- S = Q @ K^T ----
        float sc[8][4];
#pragma unroll
        for (int nt = 0; nt < 8; nt++)
#pragma unroll
            for (int i = 0; i < 4; i++) sc[nt][i] = 0.0f;

#pragma unroll
        for (int kt = 0; kt < 4; kt++) {
            uint32_t kf[8][2];
#pragma unroll
            for (int p = 0; p < 4; p++)
                ldsm_x4(kf[2 * p][0], kf[2 * p][1],
                        kf[2 * p + 1][0], kf[2 * p + 1][1],
                        Kb + offK[p] + (uint32_t)(kt * 32));
#pragma unroll
            for (int nt = 0; nt < 8; nt++)
                mma_f16(sc[nt][0], sc[nt][1], sc[nt][2], sc[nt][3],
                        qa[kt][0], qa[kt][1], qa[kt][2], qa[kt][3],
                        kf[nt][0], kf[nt][1]);
        }

        // ---- Gaussian bias + online softmax ----
        const float d0f = (float)(qw + lr - k0);
        const float d1f = d0f + 8.0f;
        float rmax0 = -INFINITY, rmax1 = -INFINITY;
#pragma unroll
        for (int nt = 0; nt < 8; nt++) {
#pragma unroll
            for (int e = 0; e < 2; e++) {
                float cj = (float)(nt * 8 + colb + e);
                float fd0 = d0f - cj;
                float fd1 = d1f - cj;
                sc[nt][e]     = fmaf(fd0 * fd0, ninv, sc[nt][e]);
                sc[nt][e + 2] = fmaf(fd1 * fd1, ninv, sc[nt][e + 2]);
                rmax0 = fmaxf(rmax0, sc[nt][e]);
                rmax1 = fmaxf(rmax1, sc[nt][e + 2]);
            }
        }
        rmax0 = fmaxf(rmax0, __shfl_xor_sync(0xffffffffu, rmax0, 1));
        rmax0 = fmaxf(rmax0, __shfl_xor_sync(0xffffffffu, rmax0, 2));
        rmax1 = fmaxf(rmax1, __shfl_xor_sync(0xffffffffu, rmax1, 1));
        rmax1 = fmaxf(rmax1, __shfl_xor_sync(0xffffffffu, rmax1, 2));

        const float mn0 = fmaxf(m0, rmax0);
        const float mn1 = fmaxf(m1, rmax1);
        const float corr0 = __expf(m0 - mn0);
        const float corr1 = __expf(m1 - mn1);
        m0 = mn0; m1 = mn1;

        uint32_t plo[8], phi[8];
        float ls0 = 0.0f, ls1 = 0.0f;
#pragma unroll
        for (int nt = 0; nt < 8; nt++) {
            float p0 = __expf(sc[nt][0] - mn0);
            float p1 = __expf(sc[nt][1] - mn0);
            float p2 = __expf(sc[nt][2] - mn1);
            float p3 = __expf(sc[nt][3] - mn1);
            __half2 hl = __floats2half2_rn(p0, p1);
            __half2 hh = __floats2half2_rn(p2, p3);
            float2 fl = __half22float2(hl);
            float2 fh = __half22float2(hh);
            ls0 += fl.x + fl.y;
            ls1 += fh.x + fh.y;
            plo[nt] = h2u(hl);
            phi[nt] = h2u(hh);
        }
        l0 = l0 * corr0 + ls0;
        l1 = l1 * corr1 + ls1;

        if (__ballot_sync(0xffffffffu, (corr0 != 1.0f) | (corr1 != 1.0f))) {
#pragma unroll
            for (int nt = 0; nt < 8; nt++) {
                o[nt][0] *= corr0; o[nt][1] *= corr0;
                o[nt][2] *= corr1; o[nt][3] *= corr1;
            }
        }

        // ---- O += P @ V ----
#pragma unroll
        for (int kt2 = 0; kt2 < 4; kt2++) {
            uint32_t a0 = plo[2 * kt2];
            uint32_t a1 = phi[2 * kt2];
            uint32_t a2 = plo[2 * kt2 + 1];
            uint32_t a3 = phi[2 * kt2 + 1];

            uint32_t vf[8][2];
#pragma unroll
            for (int p = 0; p < 4; p++)
                ldsm_x4(vf[2 * p][0], vf[2 * p][1],
                        vf[2 * p + 1][0], vf[2 * p + 1][1],
                        Kb + offV[p] + (uint32_t)(kt2 * 32));
#pragma unroll
            for (int nt = 0; nt < 8; nt++)
                mma_f16(o[nt][0], o[nt][1], o[nt][2], o[nt][3],
                        a0, a1, a2, a3, vf[nt][0], vf[nt][1]);
        }

        cur ^= 1;
    }

    l0 += __shfl_xor_sync(0xffffffffu, l0, 1);
    l0 += __shfl_xor_sync(0xffffffffu, l0, 2);
    l1 += __shfl_xor_sync(0xffffffffu, l1, 1);
    l1 += __shfl_xor_sync(0xffffffffu, l1, 2);
    const float il0 = 1.0f / l0;
    const float il1 = 1.0f / l1;

    __half* op0 = g_att + (size_t)(b * Sn + qw + lr) * En + h * Dn + colb;
    __half* op1 = op0 + 8 * En;
#pragma unroll
    for (int nt = 0; nt < 8; nt++) {
        *reinterpret_cast<uint32_t*>(op0 + nt * 8) =
            h2u(__floats2half2_rn(o[nt][0] * il0, o[nt][1] * il0));
        *reinterpret_cast<uint32_t*>(op1 + nt * 8) =
            h2u(__floats2half2_rn(o[nt][2] * il1, o[nt][3] * il1));
    }
}

// ===========================================================================
// Launch: two-stream batch-split pipeline (fork/join via events, capture-safe)
// ===========================================================================
extern "C" void kernel_launch(void* const* d_in, const int* in_sizes, int n_in,
                              void* d_out, int out_size)
{
    const float* x  = (const float*)d_in[0];
    const float* w1 = (const float*)d_in[1];
    const float* b1 = (const float*)d_in[2];
    const float* w2 = (const float*)d_in[3];
    const float* b2 = (const float*)d_in[4];
    const float* t  = (const float*)d_in[5];
    float* out = (float*)d_out;
    (void)in_sizes; (void)n_in; (void)out_size;

    // One-time setup (first call is the uncaptured correctness run)
    static cudaStream_t sA = nullptr, sB = nullptr;
    static cudaEvent_t ev0 = nullptr, evA = nullptr, evB = nullptr;
    if (!sA) {
        cudaStreamCreateWithFlags(&sA, cudaStreamNonBlocking);
        cudaStreamCreateWithFlags(&sB, cudaStreamNonBlocking);
        cudaEventCreateWithFlags(&ev0, cudaEventDisableTiming);
        cudaEventCreateWithFlags(&evA, cudaEventDisableTiming);
        cudaEventCreateWithFlags(&evB, cudaEventDisableTiming);
        cudaFuncSetAttribute(gemm_qkv_kernel,
            cudaFuncAttributeMaxDynamicSharedMemorySize, GEMM_SMEM);
        cudaFuncSetAttribute(gemm_out_kernel,
            cudaFuncAttributeMaxDynamicSharedMemorySize, GEMM_SMEM);
        cudaFuncSetAttribute(attn_fa2_kernel,
            cudaFuncAttributeMaxDynamicSharedMemorySize, ATTN_SMEM);
    }

    // Shared prologue on the origin (default) stream
    cvt_h_kernel<<<(NXf + NW1f + NW2f) / (256 * 8), 256>>>(x, w1, w2);
    cudaEventRecord(ev0, 0);
    cudaStreamWaitEvent(sA, ev0, 0);
    cudaStreamWaitEvent(sB, ev0, 0);

    // Chain A: batch 0        | Chain B: batch 1  (disjoint memory regions)
    gemm_qkv_kernel<<<dim3(E3 / 128, Sn / 64), 128, GEMM_SMEM, sA>>>(b1, 0);
    gemm_qkv_kernel<<<dim3(E3 / 128, Sn / 64), 128, GEMM_SMEM, sB>>>(b1, Sn);

    attn_fa2_kernel<<<dim3(Sn / BR, Hn, 1), ATTN_THREADS, ATTN_SMEM, sA>>>(t, 0);
    attn_fa2_kernel<<<dim3(Sn / BR, Hn, 1), ATTN_THREADS, ATTN_SMEM, sB>>>(t, 1);

    gemm_out_kernel<<<dim3(En / 128, Sn / 64), 128, GEMM_SMEM, sA>>>(b2, out, 0);
    gemm_out_kernel<<<dim3(En / 128, Sn / 64), 128, GEMM_SMEM, sB>>>(b2, out, Sn);

    // Join back to the origin stream
    cudaEventRecord(evA, sA);
    cudaEventRecord(evB, sB);
    cudaStreamWaitEvent(0, evA, 0);
    cudaStreamWaitEvent(0, evB, 0);
}

// round 16
// speedup vs baseline: 1.1376x; 1.0202x over previous
#include <cuda_runtime.h>
#include <cuda_fp16.h>
#include <math.h>
#include <stdint.h>

// Problem constants
#define Bn  2
#define Sn  4096
#define En  512
#define Hn  8
#define Dn  64
#define E3  1536
#define Mrows (Bn * Sn)   // 8192

// Scratch (static device globals -- no allocation at runtime)
__device__ __half g_qkv[(size_t)Mrows * E3];        // [B*S,3E] fp16 (V unused)
__device__ __half g_vt [(size_t)Bn * Hn * Dn * Sn]; // V transposed [b][h][d][s]
__device__ __half g_att[(size_t)Mrows * En];        // attention out fp16
__device__ __half g_xh [(size_t)Mrows * En];        // x  fp16
__device__ __half g_w1h[(size_t)E3 * En];           // w1 fp16
__device__ __half g_w2h[(size_t)En * En];           // w2 fp16

// ===========================================================================
// Helpers
// ===========================================================================
__device__ __forceinline__ uint32_t smem_u32(const void* p) {
    uint32_t a;
    asm("{ .reg .u64 t; cvta.to.shared.u64 t, %1; cvt.u32.u64 %0, t; }"
        : "=r"(a) : "l"(p));
    return a;
}
__device__ __forceinline__ void cp16(uint32_t d, const void* s) {
    asm volatile("cp.async.cg.shared.global [%0], [%1], 16;"
                 :: "r"(d), "l"(s));
}
#define CP_COMMIT() asm volatile("cp.async.commit_group;" ::: "memory")
#define CP_WAIT0()  asm volatile("cp.async.wait_group 0;" ::: "memory")

__device__ __forceinline__ uint32_t h2u(__half2 h) {
    return *reinterpret_cast<uint32_t*>(&h);
}
// 2^x on packed fp16 pair (one MUFU op for two values)
__device__ __forceinline__ uint32_t ex2_h2(uint32_t a) {
    uint32_t r;
    asm("ex2.approx.f16x2 %0, %1;" : "=r"(r) : "r"(a));
    return r;
}
__device__ __forceinline__ float ex2f(float x) {
    float r;
    asm("ex2.approx.f32 %0, %1;" : "=f"(r) : "f"(x));
    return r;
}

// fp16 mma m16n8k16, fp32 accumulate
__device__ __forceinline__ void mma_f16(
    float& c0, float& c1, float& c2, float& c3,
    uint32_t a0, uint32_t a1, uint32_t a2, uint32_t a3,
    uint32_t b0, uint32_t b1)
{
    asm volatile(
        "mma.sync.aligned.m16n8k16.row.col.f32.f16.f16.f32 "
        "{%0,%1,%2,%3}, {%4,%5,%6,%7}, {%8,%9}, {%0,%1,%2,%3};"
        : "+f"(c0), "+f"(c1), "+f"(c2), "+f"(c3)
        : "r"(a0), "r"(a1), "r"(a2), "r"(a3), "r"(b0), "r"(b1));
}

// ldmatrix x4: four 8x8 b16 matrices
__device__ __forceinline__ void ldsm_x4(uint32_t& r0, uint32_t& r1,
                                        uint32_t& r2, uint32_t& r3,
                                        uint32_t addr)
{
    asm volatile("ldmatrix.sync.aligned.m8n8.x4.shared.b16 {%0,%1,%2,%3}, [%4];"
                 : "=r"(r0), "=r"(r1), "=r"(r2), "=r"(r3) : "r"(addr));
}

// ===========================================================================
// Convert x, w1, w2 to fp16 (8 floats per thread)
// ===========================================================================
#define NXf  (Mrows * En)          // 4194304
#define NW1f (E3 * En)             // 786432
#define NW2f (En * En)             // 262144

__global__ void __launch_bounds__(256)
cvt_h_kernel(const float* __restrict__ x, const float* __restrict__ w1,
             const float* __restrict__ w2)
{
    int i = blockIdx.x * 256 + threadIdx.x;
    int base = i * 8;
    const float* s;
    __half* d;
    if (base < NXf) {
        s = x + base;                 d = g_xh + base;
    } else if (base < NXf + NW1f) {
        s = w1 + (base - NXf);        d = g_w1h + (base - NXf);
    } else {
        s = w2 + (base - NXf - NW1f); d = g_w2h + (base - NXf - NW1f);
    }
    float4 v0 = *reinterpret_cast<const float4*>(s);
    float4 v1 = *reinterpret_cast<const float4*>(s + 4);
    uint4 o;
    o.x = h2u(__floats2half2_rn(v0.x, v0.y));
    o.y = h2u(__floats2half2_rn(v0.z, v0.w));
    o.z = h2u(__floats2half2_rn(v1.x, v1.y));
    o.w = h2u(__floats2half2_rn(v1.z, v1.w));
    *reinterpret_cast<uint4*>(d) = o;
}

// ===========================================================================
// fp16 GEMM, cp.async 2-stage, BK=64 halves, ldmatrix, m16n8k16.
// R12-exact config (best measured): CTA 64x128, 128 threads / 4 warps
// (warp tile 64x32, wm=0). mOff selects the batch half (stream split).
// C[M,N] = A[M,K] @ Bw[N,K]^T + bias[N].
// VT: qkv V-columns (nBase >= 1024) go TRANSPOSED (fp16) to g_vt.
// ===========================================================================
#define GPh 72   // smem pitch in halves (64 + 8); 144B rows -> conflict-free
#define GROWS 192                             // 64 A rows + 128 W rows
#define GSTAGE_B (GROWS * GPh * 2)            // 27648 B
#define GEMM_SMEM (2 * GSTAGE_B)              // 55296 B
#define TP 68    // transpose scratch pitch (floats, 64 rows + 4)

template<bool HALF_OUT, bool VT>
__device__ __forceinline__ void h16_gemm(
    const __half* __restrict__ A, const __half* __restrict__ Bw,
    const float* __restrict__ bias, void* __restrict__ Cv,
    int M, int N, int K, int mOff)
{
    extern __shared__ float gsm[];
    const int tid  = threadIdx.x;
    const int lane = tid & 31;
    const int wid  = tid >> 5;         // 0..3
    const int wn   = wid;              // all warps tile N; wm = 0
    const int lr   = lane >> 2;
    const int lc   = lane & 3;
    const int mBase = blockIdx.y * 64 + mOff;
    const int nBase = blockIdx.x * 128;
    const uint32_t smb = smem_u32(gsm);

    float acc[4][4][4];
#pragma unroll
    for (int mt = 0; mt < 4; mt++)
#pragma unroll
        for (int nt = 0; nt < 4; nt++)
#pragma unroll
            for (int i = 0; i < 4; i++) acc[mt][nt][i] = 0.0f;

    const __half* Abase = A  + (size_t)mBase * K;
    const __half* Wbase = Bw + (size_t)nBase * K;

    // ldmatrix per-lane offsets (bytes within a stage)
    const int lrow16 = lane & 15;
    const int kgrpA  = (lane >> 4) * 8;                       // halves
    const int rowB2  = (lane & 7) + ((lane >> 4) & 1) * 8;
    const int kofB8  = ((lane >> 3) & 1) * 8;                 // halves
    uint32_t offA[4], offB[2];
#pragma unroll
    for (int mt = 0; mt < 4; mt++)
        offA[mt] = (uint32_t)(((mt * 16 + lrow16) * GPh + kgrpA) * 2);
#pragma unroll
    for (int p = 0; p < 2; p++)
        offB[p] = (uint32_t)((64 * GPh + (wn * 32 + p * 16 + rowB2) * GPh + kofB8) * 2);

    const int nIter = K >> 6;
    // Loader: 12 cp16 per thread per stage (192 rows x 64 halves)
    auto issue = [&](int it, int s) {
        if (it < nIter) {
            uint32_t sb = smb + (uint32_t)s * GSTAGE_B;
            int kt = it << 6;
#pragma unroll
            for (int i = 0; i < 12; i++) {
                int f   = tid + i * 128;       // 0..1535
                int row = f >> 3;              // 0..191
                int c8  = (f & 7) << 3;        // 0..56 halves
                const __half* src = (row < 64)
                    ? (Abase + (size_t)row * K + kt + c8)
                    : (Wbase + (size_t)(row - 64) * K + kt + c8);
                cp16(sb + (uint32_t)(row * GPh + c8) * 2u, src);
            }
        }
        CP_COMMIT();
    };
    issue(0, 0);

    for (int it = 0; it < nIter; it++) {
        CP_WAIT0();
        __syncthreads();
        issue(it + 1, (it + 1) & 1);

        const uint32_t stb = smb + (uint32_t)(it & 1) * GSTAGE_B;
#pragma unroll
        for (int k16 = 0; k16 < 4; k16++) {
            const uint32_t kb = (uint32_t)(k16 * 32);   // 16 halves = 32 B
            uint32_t af[4][4], bf[4][2];
#pragma unroll
            for (int mt = 0; mt < 4; mt++)
                ldsm_x4(af[mt][0], af[mt][1], af[mt][2], af[mt][3],
                        stb + offA[mt] + kb);
#pragma unroll
            for (int p = 0; p < 2; p++)
                ldsm_x4(bf[2 * p][0], bf[2 * p][1],
                        bf[2 * p + 1][0], bf[2 * p + 1][1],
                        stb + offB[p] + kb);
#pragma unroll
            for (int mt = 0; mt < 4; mt++)
#pragma unroll
                for (int nt = 0; nt < 4; nt++)
                    mma_f16(acc[mt][nt][0], acc[mt][nt][1],
                            acc[mt][nt][2], acc[mt][nt][3],
                            af[mt][0], af[mt][1], af[mt][2], af[mt][3],
                            bf[nt][0], bf[nt][1]);
        }
    }

    if (VT && nBase >= 2 * En) {
        // ---- V tile (64 x 128): bias, transpose via smem, write g_vt ----
        CP_WAIT0();
        __syncthreads();
        float* T = gsm;                    // [128 cols][TP rows(64+4)]
#pragma unroll
        for (int mt = 0; mt < 4; mt++) {
            const int r0 = mt * 16 + lr;
#pragma unroll
            for (int nt = 0; nt < 4; nt++) {
                const int c = wn * 32 + nt * 8 + 2 * lc;
                const float bx = bias[nBase + c];
                const float by = bias[nBase + c + 1];
                T[c * TP + r0]           = acc[mt][nt][0] + bx;
                T[(c + 1) * TP + r0]     = acc[mt][nt][1] + by;
                T[c * TP + r0 + 8]       = acc[mt][nt][2] + bx;
                T[(c + 1) * TP + r0 + 8] = acc[mt][nt][3] + by;
            }
        }
        __syncthreads();
        const int bb = mBase >> 12;
        const int s0 = mBase & (Sn - 1);
#pragma unroll
        for (int i = 0; i < 8; i++) {
            int f  = tid + i * 128;        // 0..1023
            int c  = f >> 3;               // 0..127 local col (h,d)
            int r8 = (f & 7) << 3;         // 0..56 local row (seq)
            int col = nBase - 2 * En + c;
            int h = col >> 6, d = col & 63;
            const float* tp = T + c * TP + r8;
            uint4 o;
            o.x = h2u(__floats2half2_rn(tp[0], tp[1]));
            o.y = h2u(__floats2half2_rn(tp[2], tp[3]));
            o.z = h2u(__floats2half2_rn(tp[4], tp[5]));
            o.w = h2u(__floats2half2_rn(tp[6], tp[7]));
            *reinterpret_cast<uint4*>(
                g_vt + (((size_t)bb * Hn + h) * Dn + d) * Sn + s0 + r8) = o;
        }
        return;
    }

    // ---- normal epilogue ----
#pragma unroll
    for (int mt = 0; mt < 4; mt++) {
        const int row0 = mBase + mt * 16 + lr;
#pragma unroll
        for (int nt = 0; nt < 4; nt++) {
            const int col = nBase + wn * 32 + nt * 8 + 2 * lc;
            const float bx = bias[col];
            const float by = bias[col + 1];
            float v0 = acc[mt][nt][0] + bx, v1 = acc[mt][nt][1] + by;
            float v2 = acc[mt][nt][2] + bx, v3 = acc[mt][nt][3] + by;
            if (HALF_OUT) {
                __half* C = (__half*)Cv;
                *reinterpret_cast<uint32_t*>(C + (size_t)row0 * N + col) =
                    h2u(__floats2half2_rn(v0, v1));
                *reinterpret_cast<uint32_t*>(C + (size_t)(row0 + 8) * N + col) =
                    h2u(__floats2half2_rn(v2, v3));
            } else {
                float* C = (float*)Cv;
                *reinterpret_cast<float2*>(C + (size_t)row0 * N + col) =
                    make_float2(v0, v1);
                *reinterpret_cast<float2*>(C + (size_t)(row0 + 8) * N + col) =
                    make_float2(v2, v3);
            }
        }
    }
}

__global__ void __launch_bounds__(128, 4)
gemm_qkv_kernel(const float* __restrict__ b1, int mOff)
{
    h16_gemm<true, true>(g_xh, g_w1h, b1, g_qkv, Mrows, E3, En, mOff);
}

__global__ void __launch_bounds__(128, 4)
gemm_out_kernel(const float* __restrict__ b2, float* __restrict__ out, int mOff)
{
    h16_gemm<false, false>(g_att, g_w2h, b2, out, Mrows, En, En, mOff);
}

// ===========================================================================
// FlashAttention-2, Gaussian-bias windowed, fp16 m16n8k16 HMMA.
// R16: softmax in LOG2 domain -- Q pre-scaled by log2e/8, bias constant
// -log2e/(2 sigma^2); p = ex2.approx.f16x2 on packed (s - m) pairs.
// Halves MUFU ops (32 -> 16 per warp-tile) and removes 32 FMULs.
// P's fp16 A-fragment layout == pairs of S C-fragments -> zero shuffles.
// Window W = 11 t^2 + 64 (dropped mass < 4e-10).
// Grid (Sn/64, Hn, 1) per batch (stream split), 128 threads, 4 CTAs/SM.
// ===========================================================================
#define BR   64
#define BC   64
#define KVPh 72                         // smem pitch (halves)
#define NKB  (Sn / BC)
#define ATTN_THREADS 128
#define KV_TILE_B (BC * KVPh * 2)       // 9216 B per operand tile
#define ATTN_SMEM (2 * 2 * KV_TILE_B)   // 36864 B
#define LOG2E 1.4426950408889634f

__global__ void __launch_bounds__(ATTN_THREADS, 4)
attn_fa2_kernel(const float* __restrict__ t, int b)
{
    extern __shared__ float sm[];
    const uint32_t smb = smem_u32(sm);

    const int tid  = threadIdx.x;
    const int lane = tid & 31;
    const int wid  = tid >> 5;             // 0..3
    const int qt = blockIdx.x, h = blockIdx.y;
    const int q0 = qt * BR;
    const int qw = q0 + wid * 16;

    const int lr = lane >> 2;
    const int lc = lane & 3;

    const float tt = t[h];
    const float sig = tt * tt;
    // bias in log2 domain: -log2e * d^2 / (2 sigma^2)
    const float ninv = -LOG2E / (2.0f * sig * sig);

    const float Wf = fminf(11.0f * sig + 64.0f, (float)Sn);
    const int   W  = (int)Wf;
    const int kb_lo = max(0, (q0 - W) >> 6);
    const int kb_hi = min(NKB - 1, (q0 + BR - 1 + W) >> 6);

    const __half* srcVbase = g_vt + ((size_t)b * Hn + h) * Dn * Sn;
    auto issue_kv = [&](int k0, int buf) {
        const __half* srcK = g_qkv + En + (size_t)(b * Sn + k0) * E3 + h * Dn;
        const __half* srcV = srcVbase + k0;
        uint32_t sb = smb + (uint32_t)buf * (2u * KV_TILE_B);
#pragma unroll
        for (int i = 0; i < 8; i++) {
            int f   = i * ATTN_THREADS + tid;   // 0..1023
            int sel = f >> 9;
            int idx = f & 511;
            int row = idx >> 3;                 // 0..63
            int c8  = (idx & 7) << 3;           // 0..56 halves
            const __half* src = sel ? (srcV + (size_t)row * Sn + c8)
                                    : (srcK + (size_t)row * E3 + c8);
            uint32_t dst = sb + (uint32_t)((sel * BC + row) * KVPh + c8) * 2u;
            cp16(dst, src);
        }
    };

    const int rowB2 = (lane & 7) + ((lane >> 4) & 1) * 8;
    const int kofB8 = ((lane >> 3) & 1) * 8;
    uint32_t offK[4], offV[4];
#pragma unroll
    for (int p = 0; p < 4; p++) {
        offK[p] = (uint32_t)(((p * 16 + rowB2) * KVPh + kofB8) * 2);
        offV[p] = offK[p] + (uint32_t)KV_TILE_B;
    }

    // Q fragments pre-scaled by log2e/8 (folds exp's log2e into QK^T)
    uint32_t qa[4][4];
    {
        const __half2 sQ = __float2half2_rn(0.125f * LOG2E);
        const __half* qp  = g_qkv + (size_t)(b * Sn + qw + lr) * E3 + h * Dn;
        const __half* qp8 = qp + 8 * E3;
#pragma unroll
        for (int kt = 0; kt < 4; kt++) {
            int k0h = kt * 16 + 2 * lc;
            qa[kt][0] = h2u(__hmul2(*(const __half2*)(qp  + k0h),     sQ));
            qa[kt][1] = h2u(__hmul2(*(const __half2*)(qp8 + k0h),     sQ));
            qa[kt][2] = h2u(__hmul2(*(const __half2*)(qp  + k0h + 8), sQ));
            qa[kt][3] = h2u(__hmul2(*(const __half2*)(qp8 + k0h + 8), sQ));
        }
    }

    float o[8][4];
#pragma unroll
    for (int nt = 0; nt < 8; nt++)
#pragma unroll
        for (int i = 0; i < 4; i++) o[nt][i] = 0.0f;
    float m0 = -INFINITY, m1 = -INFINITY;
    float l0 = 0.0f, l1 = 0.0f;

    issue_kv(kb_lo * BC, 0);
    CP_COMMIT();

    const int colb = 2 * lc;

    int cur = 0;
    for (int kb = kb_lo; kb <= kb_hi; kb++) {
        const int k0 = kb * BC;

        CP_WAIT0();
        __syncthreads();
        if (kb + 1 <= kb_hi) issue_kv(k0 + BC, cur ^ 1);
        CP_COMMIT();

        const uint32_t Kb = smb + (uint32_t)cur * (2u * KV_TILE_B);

        // ---- S = Q @ K^T (already in log2 domain) ----
        float sc[8][4];
#pragma unroll
        for (int nt = 0; nt < 8; nt++)
#pragma unroll
            for (int i = 0; i < 4; i++) sc[nt][i] = 0.0f;

#pragma unroll
        for (int kt = 0; kt < 4; kt++) {
            uint32_t kf[8][2];
#pragma unroll
            for (int p = 0; p < 4; p++)
                ldsm_x4(kf[2 * p][0], kf[2 * p][1],
                        kf[2 * p + 1][0], kf[2 * p + 1][1],
                        Kb + offK[p] + (uint32_t)(kt * 32));
#pragma unroll
            for (int nt = 0; nt < 8; nt++)
                mma_f16(sc[nt][0], sc[nt][1], sc[nt][2], sc[nt][3],
                        qa[kt][0], qa[kt][1], qa[kt][2], qa[kt][3],
                        kf[nt][0], kf[nt][1]);
        }

        // ---- Gaussian bias (log2) + online softmax ----
        const float d0f = (float)(qw + lr - k0);
        const float d1f = d0f + 8.0f;
        float rmax0 = -INFINITY, rmax1 = -INFINITY;
#pragma unroll
        for (int nt = 0; nt < 8; nt++) {
#pragma unroll
            for (int e = 0; e < 2; e++) {
                float cj = (float)(nt * 8 + colb + e);
                float fd0 = d0f - cj;
                float fd1 = d1f - cj;
                sc[nt][e]     = fmaf(fd0 * fd0, ninv, sc[nt][e]);
                sc[nt][e + 2] = fmaf(fd1 * fd1, ninv, sc[nt][e + 2]);
                rmax0 = fmaxf(rmax0, sc[nt][e]);
                rmax1 = fmaxf(rmax1, sc[nt][e + 2]);
            }
        }
        rmax0 = fmaxf(rmax0, __shfl_xor_sync(0xffffffffu, rmax0, 1));
        rmax0 = fmaxf(rmax0, __shfl_xor_sync(0xffffffffu, rmax0, 2));
        rmax1 = fmaxf(rmax1, __shfl_xor_sync(0xffffffffu, rmax1, 1));
        rmax1 = fmaxf(rmax1, __shfl_xor_sync(0xffffffffu, rmax1, 2));

        const float mn0 = fmaxf(m0, rmax0);
        const float mn1 = fmaxf(m1, rmax1);
        const float corr0 = ex2f(m0 - mn0);
        const float corr1 = ex2f(m1 - mn1);
        m0 = mn0; m1 = mn1;

        // P = 2^(s - m): pack args to fp16 pairs, one ex2.f16x2 per pair.
        // l sums the SAME values that feed PV, so O/l cancels exactly.
        uint32_t plo[8], phi[8];
        float ls0 = 0.0f, ls1 = 0.0f;
#pragma unroll
        for (int nt = 0; nt < 8; nt++) {
            uint32_t al = h2u(__floats2half2_rn(sc[nt][0] - mn0,
                                                sc[nt][1] - mn0));
            uint32_t ah = h2u(__floats2half2_rn(sc[nt][2] - mn1,
                                                sc[nt][3] - mn1));
            uint32_t pl = ex2_h2(al);
            uint32_t ph = ex2_h2(ah);
            float2 fl = __half22float2(*reinterpret_cast<__half2*>(&pl));
            float2 fh = __half22float2(*reinterpret_cast<__half2*>(&ph));
            ls0 += fl.x + fl.y;
            ls1 += fh.x + fh.y;
            plo[nt] = pl;
            phi[nt] = ph;
        }
        l0 = l0 * corr0 + ls0;
        l1 = l1 * corr1 + ls1;

        if (__ballot_sync(0xffffffffu, (corr0 != 1.0f) | (corr1 != 1.0f))) {
#pragma unroll
            for (int nt = 0; nt < 8; nt++) {
                o[nt][0] *= corr0; o[nt][1] *= corr0;
                o[nt][2] *= corr1; o[nt][3] *= corr1;
            }
        }

        // ---- O += P @ V ----
#pragma unroll
        for (int kt2 = 0; kt2 < 4; kt2++) {
            uint32_t a0 = plo[2 * kt2];
            uint32_t a1 = phi[2 * kt2];
            uint32_t a2 = plo[2 * kt2 + 1];
            uint32_t a3 = phi[2 * kt2 + 1];

            uint32_t vf[8][2];
#pragma unroll
            for (int p = 0; p < 4; p++)
                ldsm_x4(vf[2 * p][0], vf[2 * p][1],
                        vf[2 * p + 1][0], vf[2 * p + 1][1],
                        Kb + offV[p] + (uint32_t)(kt2 * 32));
#pragma unroll
            for (int nt = 0; nt < 8; nt++)
                mma_f16(o[nt][0], o[nt][1], o[nt][2], o[nt][3],
                        a0, a1, a2, a3, vf[nt][0], vf[nt][1]);
        }

        cur ^= 1;
    }

    l0 += __shfl_xor_sync(0xffffffffu, l0, 1);
    l0 += __shfl_xor_sync(0xffffffffu, l0, 2);
    l1 += __shfl_xor_sync(0xffffffffu, l1, 1);
    l1 += __shfl_xor_sync(0xffffffffu, l1, 2);
    const float il0 = 1.0f / l0;
    const float il1 = 1.0f / l1;

    __half* op0 = g_att + (size_t)(b * Sn + qw + lr) * En + h * Dn + colb;
    __half* op1 = op0 + 8 * En;
#pragma unroll
    for (int nt = 0; nt < 8; nt++) {
        *reinterpret_cast<uint32_t*>(op0 + nt * 8) =
            h2u(__floats2half2_rn(o[nt][0] * il0, o[nt][1] * il0));
        *reinterpret_cast<uint32_t*>(op1 + nt * 8) =
            h2u(__floats2half2_rn(o[nt][2] * il1, o[nt][3] * il1));
    }
}

// ===========================================================================
// Launch: two-stream batch-split pipeline (fork/join via events, capture-safe)
// ===========================================================================
extern "C" void kernel_launch(void* const* d_in, const int* in_sizes, int n_in,
                              void* d_out, int out_size)
{
    const float* x  = (const float*)d_in[0];
    const float* w1 = (const float*)d_in[1];
    const float* b1 = (const float*)d_in[2];
    const float* w2 = (const float*)d_in[3];
    const float* b2 = (const float*)d_in[4];
    const float* t  = (const float*)d_in[5];
    float* out = (float*)d_out;
    (void)in_sizes; (void)n_in; (void)out_size;

    // One-time setup (first call is the uncaptured correctness run)
    static cudaStream_t sA = nullptr, sB = nullptr;
    static cudaEvent_t ev0 = nullptr, evA = nullptr, evB = nullptr;
    if (!sA) {
        cudaStreamCreateWithFlags(&sA, cudaStreamNonBlocking);
        cudaStreamCreateWithFlags(&sB, cudaStreamNonBlocking);
        cudaEventCreateWithFlags(&ev0, cudaEventDisableTiming);
        cudaEventCreateWithFlags(&evA, cudaEventDisableTiming);
        cudaEventCreateWithFlags(&evB, cudaEventDisableTiming);
        cudaFuncSetAttribute(gemm_qkv_kernel,
            cudaFuncAttributeMaxDynamicSharedMemorySize, GEMM_SMEM);
        cudaFuncSetAttribute(gemm_out_kernel,
            cudaFuncAttributeMaxDynamicSharedMemorySize, GEMM_SMEM);
        cudaFuncSetAttribute(attn_fa2_kernel,
            cudaFuncAttributeMaxDynamicSharedMemorySize, ATTN_SMEM);
    }

    // Shared prologue on the origin (default) stream
    cvt_h_kernel<<<(NXf + NW1f + NW2f) / (256 * 8), 256>>>(x, w1, w2);
    cudaEventRecord(ev0, 0);
    cudaStreamWaitEvent(sA, ev0, 0);
    cudaStreamWaitEvent(sB, ev0, 0);

    // Chain A: batch 0        | Chain B: batch 1  (disjoint memory regions)
    gemm_qkv_kernel<<<dim3(E3 / 128, Sn / 64), 128, GEMM_SMEM, sA>>>(b1, 0);
    gemm_qkv_kernel<<<dim3(E3 / 128, Sn / 64), 128, GEMM_SMEM, sB>>>(b1, Sn);

    attn_fa2_kernel<<<dim3(Sn / BR, Hn, 1), ATTN_THREADS, ATTN_SMEM, sA>>>(t, 0);
    attn_fa2_kernel<<<dim3(Sn / BR, Hn, 1), ATTN_THREADS, ATTN_SMEM, sB>>>(t, 1);

    gemm_out_kernel<<<dim3(En / 128, Sn / 64), 128, GEMM_SMEM, sA>>>(b2, out, 0);
    gemm_out_kernel<<<dim3(En / 128, Sn / 64), 128, GEMM_SMEM, sB>>>(b2, out, Sn);

    // Join back to the origin stream
    cudaEventRecord(evA, sA);
    cudaEventRecord(evB, sB);
    cudaStreamWaitEvent(0, evA, 0);
    cudaStreamWaitEvent(0, evB, 0);
}

// round 17
// speedup vs baseline: 1.2528x; 1.1013x over previous
#include <cuda_runtime.h>
#include <cuda_fp16.h>
#include <math.h>
#include <stdint.h>

// Problem constants
#define Bn  2
#define Sn  4096
#define En  512
#define Hn  8
#define Dn  64
#define E3  1536
#define Mrows (Bn * Sn)   // 8192

// Scratch (static device globals -- no allocation at runtime)
__device__ __half g_qkv[(size_t)Mrows * E3];        // [B*S,3E] fp16 (V unused)
__device__ __half g_vt [(size_t)Bn * Hn * Dn * Sn]; // V transposed [b][h][d][s]
__device__ __half g_att[(size_t)Mrows * En];        // attention out fp16
__device__ __half g_xh [(size_t)Mrows * En];        // x  fp16
__device__ __half g_w1h[(size_t)E3 * En];           // w1 fp16
__device__ __half g_w2h[(size_t)En * En];           // w2 fp16

// ===========================================================================
// Helpers
// ===========================================================================
__device__ __forceinline__ uint32_t smem_u32(const void* p) {
    uint32_t a;
    asm("{ .reg .u64 t; cvta.to.shared.u64 t, %1; cvt.u32.u64 %0, t; }"
        : "=r"(a) : "l"(p));
    return a;
}
__device__ __forceinline__ void cp16(uint32_t d, const void* s) {
    asm volatile("cp.async.cg.shared.global [%0], [%1], 16;"
                 :: "r"(d), "l"(s));
}
#define CP_COMMIT() asm volatile("cp.async.commit_group;" ::: "memory")
#define CP_WAIT0()  asm volatile("cp.async.wait_group 0;" ::: "memory")

__device__ __forceinline__ uint32_t h2u(__half2 h) {
    return *reinterpret_cast<uint32_t*>(&h);
}
// 2^x on packed fp16 pair (one MUFU op for two values)
__device__ __forceinline__ uint32_t ex2_h2(uint32_t a) {
    uint32_t r;
    asm("ex2.approx.f16x2 %0, %1;" : "=r"(r) : "r"(a));
    return r;
}
__device__ __forceinline__ float ex2f(float x) {
    float r;
    asm("ex2.approx.f32 %0, %1;" : "=f"(r) : "f"(x));
    return r;
}

// fp16 mma m16n8k16, fp32 accumulate
__device__ __forceinline__ void mma_f16(
    float& c0, float& c1, float& c2, float& c3,
    uint32_t a0, uint32_t a1, uint32_t a2, uint32_t a3,
    uint32_t b0, uint32_t b1)
{
    asm volatile(
        "mma.sync.aligned.m16n8k16.row.col.f32.f16.f16.f32 "
        "{%0,%1,%2,%3}, {%4,%5,%6,%7}, {%8,%9}, {%0,%1,%2,%3};"
        : "+f"(c0), "+f"(c1), "+f"(c2), "+f"(c3)
        : "r"(a0), "r"(a1), "r"(a2), "r"(a3), "r"(b0), "r"(b1));
}

// ldmatrix x4: four 8x8 b16 matrices
__device__ __forceinline__ void ldsm_x4(uint32_t& r0, uint32_t& r1,
                                        uint32_t& r2, uint32_t& r3,
                                        uint32_t addr)
{
    asm volatile("ldmatrix.sync.aligned.m8n8.x4.shared.b16 {%0,%1,%2,%3}, [%4];"
                 : "=r"(r0), "=r"(r1), "=r"(r2), "=r"(r3) : "r"(addr));
}

// ===========================================================================
// Convert x, w1, w2 to fp16 (8 floats per thread)
// ===========================================================================
#define NXf  (Mrows * En)          // 4194304
#define NW1f (E3 * En)             // 786432
#define NW2f (En * En)             // 262144

__global__ void __launch_bounds__(256)
cvt_h_kernel(const float* __restrict__ x, const float* __restrict__ w1,
             const float* __restrict__ w2)
{
    int i = blockIdx.x * 256 + threadIdx.x;
    int base = i * 8;
    const float* s;
    __half* d;
    if (base < NXf) {
        s = x + base;                 d = g_xh + base;
    } else if (base < NXf + NW1f) {
        s = w1 + (base - NXf);        d = g_w1h + (base - NXf);
    } else {
        s = w2 + (base - NXf - NW1f); d = g_w2h + (base - NXf - NW1f);
    }
    float4 v0 = *reinterpret_cast<const float4*>(s);
    float4 v1 = *reinterpret_cast<const float4*>(s + 4);
    uint4 o;
    o.x = h2u(__floats2half2_rn(v0.x, v0.y));
    o.y = h2u(__floats2half2_rn(v0.z, v0.w));
    o.z = h2u(__floats2half2_rn(v1.x, v1.y));
    o.w = h2u(__floats2half2_rn(v1.z, v1.w));
    *reinterpret_cast<uint4*>(d) = o;
}

// ===========================================================================
// fp16 GEMM, cp.async 2-stage, BK=64 halves, ldmatrix, m16n8k16.
// R12-exact config (best measured): CTA 64x128, 128 threads / 4 warps
// (warp tile 64x32, wm=0). mOff selects the batch half (stream split).
// C[M,N] = A[M,K] @ Bw[N,K]^T + bias[N].
// VT: qkv V-columns (nBase >= 1024) go TRANSPOSED (fp16) to g_vt.
// ===========================================================================
#define GPh 72   // smem pitch in halves (64 + 8); 144B rows -> conflict-free
#define GROWS 192                             // 64 A rows + 128 W rows
#define GSTAGE_B (GROWS * GPh * 2)            // 27648 B
#define GEMM_SMEM (2 * GSTAGE_B)              // 55296 B
#define TP 68    // transpose scratch pitch (floats, 64 rows + 4)

template<bool HALF_OUT, bool VT>
__device__ __forceinline__ void h16_gemm(
    const __half* __restrict__ A, const __half* __restrict__ Bw,
    const float* __restrict__ bias, void* __restrict__ Cv,
    int M, int N, int K, int mOff)
{
    extern __shared__ float gsm[];
    const int tid  = threadIdx.x;
    const int lane = tid & 31;
    const int wid  = tid >> 5;         // 0..3
    const int wn   = wid;              // all warps tile N; wm = 0
    const int lr   = lane >> 2;
    const int lc   = lane & 3;
    const int mBase = blockIdx.y * 64 + mOff;
    const int nBase = blockIdx.x * 128;
    const uint32_t smb = smem_u32(gsm);

    float acc[4][4][4];
#pragma unroll
    for (int mt = 0; mt < 4; mt++)
#pragma unroll
        for (int nt = 0; nt < 4; nt++)
#pragma unroll
            for (int i = 0; i < 4; i++) acc[mt][nt][i] = 0.0f;

    const __half* Abase = A  + (size_t)mBase * K;
    const __half* Wbase = Bw + (size_t)nBase * K;

    // ldmatrix per-lane offsets (bytes within a stage)
    const int lrow16 = lane & 15;
    const int kgrpA  = (lane >> 4) * 8;                       // halves
    const int rowB2  = (lane & 7) + ((lane >> 4) & 1) * 8;
    const int kofB8  = ((lane >> 3) & 1) * 8;                 // halves
    uint32_t offA[4], offB[2];
#pragma unroll
    for (int mt = 0; mt < 4; mt++)
        offA[mt] = (uint32_t)(((mt * 16 + lrow16) * GPh + kgrpA) * 2);
#pragma unroll
    for (int p = 0; p < 2; p++)
        offB[p] = (uint32_t)((64 * GPh + (wn * 32 + p * 16 + rowB2) * GPh + kofB8) * 2);

    const int nIter = K >> 6;
    // Loader: 12 cp16 per thread per stage (192 rows x 64 halves)
    auto issue = [&](int it, int s) {
        if (it < nIter) {
            uint32_t sb = smb + (uint32_t)s * GSTAGE_B;
            int kt = it << 6;
#pragma unroll
            for (int i = 0; i < 12; i++) {
                int f   = tid + i * 128;       // 0..1535
                int row = f >> 3;              // 0..191
                int c8  = (f & 7) << 3;        // 0..56 halves
                const __half* src = (row < 64)
                    ? (Abase + (size_t)row * K + kt + c8)
                    : (Wbase + (size_t)(row - 64) * K + kt + c8);
                cp16(sb + (uint32_t)(row * GPh + c8) * 2u, src);
            }
        }
        CP_COMMIT();
    };
    issue(0, 0);

    for (int it = 0; it < nIter; it++) {
        CP_WAIT0();
        __syncthreads();
        issue(it + 1, (it + 1) & 1);

        const uint32_t stb = smb + (uint32_t)(it & 1) * GSTAGE_B;
#pragma unroll
        for (int k16 = 0; k16 < 4; k16++) {
            const uint32_t kb = (uint32_t)(k16 * 32);   // 16 halves = 32 B
            uint32_t af[4][4], bf[4][2];
#pragma unroll
            for (int mt = 0; mt < 4; mt++)
                ldsm_x4(af[mt][0], af[mt][1], af[mt][2], af[mt][3],
                        stb + offA[mt] + kb);
#pragma unroll
            for (int p = 0; p < 2; p++)
                ldsm_x4(bf[2 * p][0], bf[2 * p][1],
                        bf[2 * p + 1][0], bf[2 * p + 1][1],
                        stb + offB[p] + kb);
#pragma unroll
            for (int mt = 0; mt < 4; mt++)
#pragma unroll
                for (int nt = 0; nt < 4; nt++)
                    mma_f16(acc[mt][nt][0], acc[mt][nt][1],
                            acc[mt][nt][2], acc[mt][nt][3],
                            af[mt][0], af[mt][1], af[mt][2], af[mt][3],
                            bf[nt][0], bf[nt][1]);
        }
    }

    if (VT && nBase >= 2 * En) {
        // ---- V tile (64 x 128): bias, transpose via smem, write g_vt ----
        CP_WAIT0();
        __syncthreads();
        float* T = gsm;                    // [128 cols][TP rows(64+4)]
#pragma unroll
        for (int mt = 0; mt < 4; mt++) {
            const int r0 = mt * 16 + lr;
#pragma unroll
            for (int nt = 0; nt < 4; nt++) {
                const int c = wn * 32 + nt * 8 + 2 * lc;
                const float bx = bias[nBase + c];
                const float by = bias[nBase + c + 1];
                T[c * TP + r0]           = acc[mt][nt][0] + bx;
                T[(c + 1) * TP + r0]     = acc[mt][nt][1] + by;
                T[c * TP + r0 + 8]       = acc[mt][nt][2] + bx;
                T[(c + 1) * TP + r0 + 8] = acc[mt][nt][3] + by;
            }
        }
        __syncthreads();
        const int bb = mBase >> 12;
        const int s0 = mBase & (Sn - 1);
#pragma unroll
        for (int i = 0; i < 8; i++) {
            int f  = tid + i * 128;        // 0..1023
            int c  = f >> 3;               // 0..127 local col (h,d)
            int r8 = (f & 7) << 3;         // 0..56 local row (seq)
            int col = nBase - 2 * En + c;
            int h = col >> 6, d = col & 63;
            const float* tp = T + c * TP + r8;
            uint4 o;
            o.x = h2u(__floats2half2_rn(tp[0], tp[1]));
            o.y = h2u(__floats2half2_rn(tp[2], tp[3]));
            o.z = h2u(__floats2half2_rn(tp[4], tp[5]));
            o.w = h2u(__floats2half2_rn(tp[6], tp[7]));
            *reinterpret_cast<uint4*>(
                g_vt + (((size_t)bb * Hn + h) * Dn + d) * Sn + s0 + r8) = o;
        }
        return;
    }

    // ---- normal epilogue ----
#pragma unroll
    for (int mt = 0; mt < 4; mt++) {
        const int row0 = mBase + mt * 16 + lr;
#pragma unroll
        for (int nt = 0; nt < 4; nt++) {
            const int col = nBase + wn * 32 + nt * 8 + 2 * lc;
            const float bx = bias[col];
            const float by = bias[col + 1];
            float v0 = acc[mt][nt][0] + bx, v1 = acc[mt][nt][1] + by;
            float v2 = acc[mt][nt][2] + bx, v3 = acc[mt][nt][3] + by;
            if (HALF_OUT) {
                __half* C = (__half*)Cv;
                *reinterpret_cast<uint32_t*>(C + (size_t)row0 * N + col) =
                    h2u(__floats2half2_rn(v0, v1));
                *reinterpret_cast<uint32_t*>(C + (size_t)(row0 + 8) * N + col) =
                    h2u(__floats2half2_rn(v2, v3));
            } else {
                float* C = (float*)Cv;
                *reinterpret_cast<float2*>(C + (size_t)row0 * N + col) =
                    make_float2(v0, v1);
                *reinterpret_cast<float2*>(C + (size_t)(row0 + 8) * N + col) =
                    make_float2(v2, v3);
            }
        }
    }
}

__global__ void __launch_bounds__(128, 4)
gemm_qkv_kernel(const float* __restrict__ b1, int mOff)
{
    h16_gemm<true, true>(g_xh, g_w1h, b1, g_qkv, Mrows, E3, En, mOff);
}

__global__ void __launch_bounds__(128, 4)
gemm_out_kernel(const float* __restrict__ b2, float* __restrict__ out, int mOff)
{
    h16_gemm<false, false>(g_att, g_w2h, b2, out, Mrows, En, En, mOff);
}

// ===========================================================================
// FlashAttention-2, Gaussian-bias windowed, fp16 m16n8k16 HMMA.
// R17: TIGHT window W = 9*sigma (no tile slack). Dropped relative mass
// <= 4096 * exp(dS - 40.5) ~ 1e-7 even with score spread dS = 16 --
// four orders below the 1e-3 gate. Diagonal tile always included since
// kb_lo <= q0>>6 <= kb_hi. Softmax in log2 domain with ex2.approx.f16x2.
// Grid (Sn/64, Hn, 1) per batch (stream split), 128 threads, 4 CTAs/SM.
// ===========================================================================
#define BR   64
#define BC   64
#define KVPh 72                         // smem pitch (halves)
#define NKB  (Sn / BC)
#define ATTN_THREADS 128
#define KV_TILE_B (BC * KVPh * 2)       // 9216 B per operand tile
#define ATTN_SMEM (2 * 2 * KV_TILE_B)   // 36864 B
#define LOG2E 1.4426950408889634f

__global__ void __launch_bounds__(ATTN_THREADS, 4)
attn_fa2_kernel(const float* __restrict__ t, int b)
{
    extern __shared__ float sm[];
    const uint32_t smb = smem_u32(sm);

    const int tid  = threadIdx.x;
    const int lane = tid & 31;
    const int wid  = tid >> 5;             // 0..3
    const int qt = blockIdx.x, h = blockIdx.y;
    const int q0 = qt * BR;
    const int qw = q0 + wid * 16;

    const int lr = lane >> 2;
    const int lc = lane & 3;

    const float tt = t[h];
    const float sig = tt * tt;
    // bias in log2 domain: -log2e * d^2 / (2 sigma^2)
    const float ninv = -LOG2E / (2.0f * sig * sig);

    // tight locality window: W = 9 sigma (deficit 40.5 in exp domain)
    const float Wf = fminf(9.0f * sig, (float)Sn);
    const int   W  = (int)Wf;
    const int kb_lo = max(0, (q0 - W) >> 6);
    const int kb_hi = min(NKB - 1, (q0 + BR - 1 + W) >> 6);

    const __half* srcVbase = g_vt + ((size_t)b * Hn + h) * Dn * Sn;
    auto issue_kv = [&](int k0, int buf) {
        const __half* srcK = g_qkv + En + (size_t)(b * Sn + k0) * E3 + h * Dn;
        const __half* srcV = srcVbase + k0;
        uint32_t sb = smb + (uint32_t)buf * (2u * KV_TILE_B);
#pragma unroll
        for (int i = 0; i < 8; i++) {
            int f   = i * ATTN_THREADS + tid;   // 0..1023
            int sel = f >> 9;
            int idx = f & 511;
            int row = idx >> 3;                 // 0..63
            int c8  = (idx & 7) << 3;           // 0..56 halves
            const __half* src = sel ? (srcV + (size_t)row * Sn + c8)
                                    : (srcK + (size_t)row * E3 + c8);
            uint32_t dst = sb + (uint32_t)((sel * BC + row) * KVPh + c8) * 2u;
            cp16(dst, src);
        }
    };

    const int rowB2 = (lane & 7) + ((lane >> 4) & 1) * 8;
    const int kofB8 = ((lane >> 3) & 1) * 8;
    uint32_t offK[4], offV[4];
#pragma unroll
    for (int p = 0; p < 4; p++) {
        offK[p] = (uint32_t)(((p * 16 + rowB2) * KVPh + kofB8) * 2);
        offV[p] = offK[p] + (uint32_t)KV_TILE_B;
    }

    // Q fragments pre-scaled by log2e/8 (folds exp's log2e into QK^T)
    uint32_t qa[4][4];
    {
        const __half2 sQ = __float2half2_rn(0.125f * LOG2E);
        const __half* qp  = g_qkv + (size_t)(b * Sn + qw + lr) * E3 + h * Dn;
        const __half* qp8 = qp + 8 * E3;
#pragma unroll
        for (int kt = 0; kt < 4; kt++) {
            int k0h = kt * 16 + 2 * lc;
            qa[kt][0] = h2u(__hmul2(*(const __half2*)(qp  + k0h),     sQ));
            qa[kt][1] = h2u(__hmul2(*(const __half2*)(qp8 + k0h),     sQ));
            qa[kt][2] = h2u(__hmul2(*(const __half2*)(qp  + k0h + 8), sQ));
            qa[kt][3] = h2u(__hmul2(*(const __half2*)(qp8 + k0h + 8), sQ));
        }
    }

    float o[8][4];
#pragma unroll
    for (int nt = 0; nt < 8; nt++)
#pragma unroll
        for (int i = 0; i < 4; i++) o[nt][i] = 0.0f;
    float m0 = -INFINITY, m1 = -INFINITY;
    float l0 = 0.0f, l1 = 0.0f;

    issue_kv(kb_lo * BC, 0);
    CP_COMMIT();

    const int colb = 2 * lc;

    int cur = 0;
    for (int kb = kb_lo; kb <= kb_hi; kb++) {
        const int k0 = kb * BC;

        CP_WAIT0();
        __syncthreads();
        if (kb + 1 <= kb_hi) issue_kv(k0 + BC, cur ^ 1);
        CP_COMMIT();

        const uint32_t Kb = smb + (uint32_t)cur * (2u * KV_TILE_B);

        // ---- S = Q @ K^T (already in log2 domain) ----
        float sc[8][4];
#pragma unroll
        for (int nt = 0; nt < 8; nt++)
#pragma unroll
            for (int i = 0; i < 4; i++) sc[nt][i] = 0.0f;

#pragma unroll
        for (int kt = 0; kt < 4; kt++) {
            uint32_t kf[8][2];
#pragma unroll
            for (int p = 0; p < 4; p++)
                ldsm_x4(kf[2 * p][0], kf[2 * p][1],
                        kf[2 * p + 1][0], kf[2 * p + 1][1],
                        Kb + offK[p] + (uint32_t)(kt * 32));
#pragma unroll
            for (int nt = 0; nt < 8; nt++)
                mma_f16(sc[nt][0], sc[nt][1], sc[nt][2], sc[nt][3],
                        qa[kt][0], qa[kt][1], qa[kt][2], qa[kt][3],
                        kf[nt][0], kf[nt][1]);
        }

        // ---- Gaussian bias (log2) + online softmax ----
        const float d0f = (float)(qw + lr - k0);
        const float d1f = d0f + 8.0f;
        float rmax0 = -INFINITY, rmax1 = -INFINITY;
#pragma unroll
        for (int nt = 0; nt < 8; nt++) {
#pragma unroll
            for (int e = 0; e < 2; e++) {
                float cj = (float)(nt * 8 + colb + e);
                float fd0 = d0f - cj;
                float fd1 = d1f - cj;
                sc[nt][e]     = fmaf(fd0 * fd0, ninv, sc[nt][e]);
                sc[nt][e + 2] = fmaf(fd1 * fd1, ninv, sc[nt][e + 2]);
                rmax0 = fmaxf(rmax0, sc[nt][e]);
                rmax1 = fmaxf(rmax1, sc[nt][e + 2]);
            }
        }
        rmax0 = fmaxf(rmax0, __shfl_xor_sync(0xffffffffu, rmax0, 1));
        rmax0 = fmaxf(rmax0, __shfl_xor_sync(0xffffffffu, rmax0, 2));
        rmax1 = fmaxf(rmax1, __shfl_xor_sync(0xffffffffu, rmax1, 1));
        rmax1 = fmaxf(rmax1, __shfl_xor_sync(0xffffffffu, rmax1, 2));

        const float mn0 = fmaxf(m0, rmax0);
        const float mn1 = fmaxf(m1, rmax1);
        const float corr0 = ex2f(m0 - mn0);
        const float corr1 = ex2f(m1 - mn1);
        m0 = mn0; m1 = mn1;

        // P = 2^(s - m): pack args to fp16 pairs, one ex2.f16x2 per pair.
        // l sums the SAME values that feed PV, so O/l cancels exactly.
        uint32_t plo[8], phi[8];
        float ls0 = 0.0f, ls1 = 0.0f;
#pragma unroll
        for (int nt = 0; nt < 8; nt++) {
            uint32_t al = h2u(__floats2half2_rn(sc[nt][0] - mn0,
                                                sc[nt][1] - mn0));
            uint32_t ah = h2u(__floats2half2_rn(sc[nt][2] - mn1,
                                                sc[nt][3] - mn1));
            uint32_t pl = ex2_h2(al);
            uint32_t ph = ex2_h2(ah);
            float2 fl = __half22float2(*reinterpret_cast<__half2*>(&pl));
            float2 fh = __half22float2(*reinterpret_cast<__half2*>(&ph));
            ls0 += fl.x + fl.y;
            ls1 += fh.x + fh.y;
            plo[nt] = pl;
            phi[nt] = ph;
        }
        l0 = l0 * corr0 + ls0;
        l1 = l1 * corr1 + ls1;

        if (__ballot_sync(0xffffffffu, (corr0 != 1.0f) | (corr1 != 1.0f))) {
#pragma unroll
            for (int nt = 0; nt < 8; nt++) {
                o[nt][0] *= corr0; o[nt][1] *= corr0;
                o[nt][2] *= corr1; o[nt][3] *= corr1;
            }
        }

        // ---- O += P @ V ----
#pragma unroll
        for (int kt2 = 0; kt2 < 4; kt2++) {
            uint32_t a0 = plo[2 * kt2];
            uint32_t a1 = phi[2 * kt2];
            uint32_t a2 = plo[2 * kt2 + 1];
            uint32_t a3 = phi[2 * kt2 + 1];

            uint32_t vf[8][2];
#pragma unroll
            for (int p = 0; p < 4; p++)
                ldsm_x4(vf[2 * p][0], vf[2 * p][1],
                        vf[2 * p + 1][0], vf[2 * p + 1][1],
                        Kb + offV[p] + (uint32_t)(kt2 * 32));
#pragma unroll
            for (int nt = 0; nt < 8; nt++)
                mma_f16(o[nt][0], o[nt][1], o[nt][2], o[nt][3],
                        a0, a1, a2, a3, vf[nt][0], vf[nt][1]);
        }

        cur ^= 1;
    }

    l0 += __shfl_xor_sync(0xffffffffu, l0, 1);
    l0 += __shfl_xor_sync(0xffffffffu, l0, 2);
    l1 += __shfl_xor_sync(0xffffffffu, l1, 1);
    l1 += __shfl_xor_sync(0xffffffffu, l1, 2);
    const float il0 = 1.0f / l0;
    const float il1 = 1.0f / l1;

    __half* op0 = g_att + (size_t)(b * Sn + qw + lr) * En + h * Dn + colb;
    __half* op1 = op0 + 8 * En;
#pragma unroll
    for (int nt = 0; nt < 8; nt++) {
        *reinterpret_cast<uint32_t*>(op0 + nt * 8) =
            h2u(__floats2half2_rn(o[nt][0] * il0, o[nt][1] * il0));
        *reinterpret_cast<uint32_t*>(op1 + nt * 8) =
            h2u(__floats2half2_rn(o[nt][2] * il1, o[nt][3] * il1));
    }
}

// ===========================================================================
// Launch: two-stream batch-split pipeline (fork/join via events, capture-safe)
// ===========================================================================
extern "C" void kernel_launch(void* const* d_in, const int* in_sizes, int n_in,
                              void* d_out, int out_size)
{
    const float* x  = (const float*)d_in[0];
    const float* w1 = (const float*)d_in[1];
    const float* b1 = (const float*)d_in[2];
    const float* w2 = (const float*)d_in[3];
    const float* b2 = (const float*)d_in[4];
    const float* t  = (const float*)d_in[5];
    float* out = (float*)d_out;
    (void)in_sizes; (void)n_in; (void)out_size;

    // One-time setup (first call is the uncaptured correctness run)
    static cudaStream_t sA = nullptr, sB = nullptr;
    static cudaEvent_t ev0 = nullptr, evA = nullptr, evB = nullptr;
    if (!sA) {
        cudaStreamCreateWithFlags(&sA, cudaStreamNonBlocking);
        cudaStreamCreateWithFlags(&sB, cudaStreamNonBlocking);
        cudaEventCreateWithFlags(&ev0, cudaEventDisableTiming);
        cudaEventCreateWithFlags(&evA, cudaEventDisableTiming);
        cudaEventCreateWithFlags(&evB, cudaEventDisableTiming);
        cudaFuncSetAttribute(gemm_qkv_kernel,
            cudaFuncAttributeMaxDynamicSharedMemorySize, GEMM_SMEM);
        cudaFuncSetAttribute(gemm_out_kernel,
            cudaFuncAttributeMaxDynamicSharedMemorySize, GEMM_SMEM);
        cudaFuncSetAttribute(attn_fa2_kernel,
            cudaFuncAttributeMaxDynamicSharedMemorySize, ATTN_SMEM);
    }

    // Shared prologue on the origin (default) stream
    cvt_h_kernel<<<(NXf + NW1f + NW2f) / (256 * 8), 256>>>(x, w1, w2);
    cudaEventRecord(ev0, 0);
    cudaStreamWaitEvent(sA, ev0, 0);
    cudaStreamWaitEvent(sB, ev0, 0);

    // Chain A: batch 0        | Chain B: batch 1  (disjoint memory regions)
    gemm_qkv_kernel<<<dim3(E3 / 128, Sn / 64), 128, GEMM_SMEM, sA>>>(b1, 0);
    gemm_qkv_kernel<<<dim3(E3 / 128, Sn / 64), 128, GEMM_SMEM, sB>>>(b1, Sn);

    attn_fa2_kernel<<<dim3(Sn / BR, Hn, 1), ATTN_THREADS, ATTN_SMEM, sA>>>(t, 0);
    attn_fa2_kernel<<<dim3(Sn / BR, Hn, 1), ATTN_THREADS, ATTN_SMEM, sB>>>(t, 1);

    gemm_out_kernel<<<dim3(En / 128, Sn / 64), 128, GEMM_SMEM, sA>>>(b2, out, 0);
    gemm_out_kernel<<<dim3(En / 128, Sn / 64), 128, GEMM_SMEM, sB>>>(b2, out, Sn);

    // Join back to the origin stream
    cudaEventRecord(evA, sA);
    cudaEventRecord(evB, sB);
    cudaStreamWaitEvent(0, evA, 0);
    cudaStreamWaitEvent(0, evB, 0);
}